// round 14
// baseline (speedup 1.0000x reference)
#include <cuda_runtime.h>
#include <cuda_bf16.h>
#include <cstdint>
#include <math.h>

#define HH 256
#define WW 256
#define NPIX 65536          // H*W
#define CIN 512
#define HALF 256
#define PSZ 32
#define NH 8
#define NUM 64              // patches
#define EPS 1e-5f

// ==================== mma.sync / ldmatrix / cp.async helpers ====================
__device__ __forceinline__ uint32_t smem_to_u32(const void* smem_ptr) {
    uint32_t addr;
    asm("{ .reg .u64 tmp; cvta.to.shared.u64 tmp, %1; cvt.u32.u64 %0, tmp; }"
        : "=r"(addr) : "l"(smem_ptr));
    return addr;
}
__device__ __forceinline__ void ldsm4(uint32_t* r, uint32_t addr) {
    asm volatile("ldmatrix.sync.aligned.m8n8.x4.shared.b16 {%0,%1,%2,%3}, [%4];"
        : "=r"(r[0]), "=r"(r[1]), "=r"(r[2]), "=r"(r[3]) : "r"(addr));
}
__device__ __forceinline__ void ldsm4t(uint32_t* r, uint32_t addr) {
    asm volatile("ldmatrix.sync.aligned.m8n8.x4.trans.shared.b16 {%0,%1,%2,%3}, [%4];"
        : "=r"(r[0]), "=r"(r[1]), "=r"(r[2]), "=r"(r[3]) : "r"(addr));
}
__device__ __forceinline__ void mma16816(float* c, const uint32_t* a, const uint32_t* b) {
    asm volatile(
        "mma.sync.aligned.m16n8k16.row.col.f32.bf16.bf16.f32 "
        "{%0,%1,%2,%3}, {%4,%5,%6,%7}, {%8,%9}, {%0,%1,%2,%3};"
        : "+f"(c[0]), "+f"(c[1]), "+f"(c[2]), "+f"(c[3])
        : "r"(a[0]), "r"(a[1]), "r"(a[2]), "r"(a[3]), "r"(b[0]), "r"(b[1]));
}
__device__ __forceinline__ uint32_t packbf2(float lo, float hi) {
    __nv_bfloat162 h = __floats2bfloat162_rn(lo, hi);
    return *(uint32_t*)&h;
}
__device__ __forceinline__ void cpasync16(uint32_t s, const void* g) {
    asm volatile("cp.async.cg.shared.global [%0], [%1], 16;" :: "r"(s), "l"(g) : "memory");
}
__device__ __forceinline__ void cpasync_commit() {
    asm volatile("cp.async.commit_group;" ::: "memory");
}
template <int N>
__device__ __forceinline__ void cpasync_wait() {
    asm volatile("cp.async.wait_group %0;" :: "n"(N) : "memory");
}

// ==================== static scratch ====================
__device__ __nv_bfloat16 g_qthi[(size_t)NPIX * HALF];  // q transposed hi, [pix][256]
__device__ __nv_bfloat16 g_qtlo[(size_t)NPIX * HALF];
__device__ __nv_bfloat16 g_pthi[(size_t)NPIX * HALF];  // attn-out transposed hi, [pix][256]
__device__ __nv_bfloat16 g_ptlo[(size_t)NPIX * HALF];
__device__ __nv_bfloat16 g_whi[4][CIN * HALF];         // q,k,v,o weights hi
__device__ __nv_bfloat16 g_wlo[4][CIN * HALF];
__device__ __nv_bfloat16 g_ahi[(size_t)NUM * 1024 * 64];   // attn bf16 hi
__device__ __nv_bfloat16 g_alo[(size_t)NUM * 1024 * 64];   // attn bf16 lo
__device__ float g_kp[HALF * NUM];                     // pooled k [c][patch] fp32
__device__ float g_vp[NUM * HALF];                     // pooled v [patch][c] fp32
__device__ __nv_bfloat16 g_kpbh[NUM * HALF];           // kp bf16 hi, [patch][c]
__device__ __nv_bfloat16 g_kpbl[NUM * HALF];           // kp bf16 lo

// ==================== conversion kernels ====================
__global__ void conv_w4_kernel(const float* __restrict__ w0, const float* __restrict__ w1,
                               const float* __restrict__ w2, const float* __restrict__ w3,
                               __nv_bfloat16* __restrict__ hi, __nv_bfloat16* __restrict__ lo)
{
    const int wsel = blockIdx.y;
    const float* w = (wsel == 0) ? w0 : (wsel == 1) ? w1 : (wsel == 2) ? w2 : w3;
    int i = blockIdx.x * 256 + threadIdx.x;
    float v = w[i];
    __nv_bfloat16 h = __float2bfloat16(v);
    const size_t off = (size_t)wsel * (CIN * HALF) + i;
    hi[off] = h;
    lo[off] = __float2bfloat16(v - __bfloat162float(h));
}

__global__ void zero_pool_kernel(float* kp, float* vp)
{
    int i = blockIdx.x * 256 + threadIdx.x;   // grid 64 -> 16384
    kp[i] = 0.f;
    vp[i] = 0.f;
}

// kp [c][patch] fp32 -> [patch][c] bf16 hi/lo
__global__ void kconv_kernel(const float* __restrict__ kp,
                             __nv_bfloat16* __restrict__ kph, __nv_bfloat16* __restrict__ kpl)
{
    int i = blockIdx.x * 256 + threadIdx.x;   // grid 64 -> 16384
    const int patch = i >> 8;
    const int c = i & 255;
    float v = kp[c * NUM + patch];
    __nv_bfloat16 h = __float2bfloat16(v);
    kph[patch * HALF + c] = h;
    kpl[patch * HALF + c] = __float2bfloat16(v - __bfloat162float(h));
}

// ==================== fused q/k/v HMMA projection (grid = (6, 512)) ====================
// x transpose+bf16-split fused into the loader (conv_x eliminated).
// Single barrier per K-chunk: wait -> bar -> issue(ch+1) -> compute(ch) -> STS B(ch+1).
#define LDKB2 80                      // 32 bf16 = 64B + 16B pad
#define TILE2 (128 * LDKB2)           // 10240
#define BUFSET (4 * TILE2)            // 40960
#define PROJ_SMEM (2 * BUFSET)        // 81920

struct QKVParams {
    const __nv_bfloat16* whi[3];
    const __nv_bfloat16* wlo[3];
    const float* gg[3];
    const float* bb[3];
    const float* mm[3];
    const float* vv[3];
};

// convert-store one float4 (4 pixels, one k-row) into B hi/lo tiles
__device__ __forceinline__ void stconv4(char* bhi, char* blo, int pix0, int r, float4 v)
{
    float vv[4] = { v.x, v.y, v.z, v.w };
    #pragma unroll
    for (int e = 0; e < 4; e++) {
        float f = vv[e];
        __nv_bfloat16 h = __float2bfloat16(f);
        *(__nv_bfloat16*)(bhi + (pix0 + e) * LDKB2 + r * 2) = h;
        *(__nv_bfloat16*)(blo + (pix0 + e) * LDKB2 + r * 2) =
            __float2bfloat16(f - __bfloat162float(h));
    }
}

__global__ void __launch_bounds__(256, 2)
proj_qkv(QKVParams p, const float* __restrict__ xg,
         __nv_bfloat16* __restrict__ qhi, __nv_bfloat16* __restrict__ qlo,
         float* __restrict__ kpo, float* __restrict__ vpo, float qscale)
{
    extern __shared__ char smc[];
    const uint32_t sb = smem_to_u32(smc);

    const int tid = threadIdx.x;
    const int wid = tid >> 5;
    const int lane = tid & 31;
    const int wm = wid & 1;
    const int wn = wid >> 1;
    const int wsel = blockIdx.x >> 1;     // 0=q 1=k 2=v  (fast index -> L2 reuse of x)
    const int bmh = blockIdx.x & 1;       // out-ch tile
    const int pixbase = blockIdx.y * 128;

    const __nv_bfloat16* Ahi = p.whi[wsel];
    const __nv_bfloat16* Alo = p.wlo[wsel];

    float acc[4][4][4];
    #pragma unroll
    for (int mt = 0; mt < 4; mt++)
        #pragma unroll
        for (int nt = 0; nt < 4; nt++)
            #pragma unroll
            for (int e = 0; e < 4; e++) acc[mt][nt][e] = 0.f;

    const int am_ = lane & 15;
    const int ak_ = (lane >> 4) * 8;
    const int bn_ = (lane & 7) + ((lane >> 4) << 3);
    const int bk_ = ((lane >> 3) & 1) * 8;

    // A loader: 2 tensors x 512 16B-chunks, 2 chunks/thread/tensor
    const int lr[2] = { tid >> 2, (tid + 256) >> 2 };
    const int lc = tid & 3;
    // x loader: 1024 float4 per chunk (32 k-rows x 32 groups), 4/thread
    const int xrow[4] = { tid >> 5, (tid + 256) >> 5, (tid + 512) >> 5, (tid + 768) >> 5 };
    const int xc4 = tid & 31;

    const int NCH = CIN / 32;   // 16

    // ---- prologue: A chunk0 via cp.async; x chunk0 LDG -> convert STS ----
    {
        #pragma unroll
        for (int j = 0; j < 2; j++) {
            const size_t arow = (size_t)(bmh * 128 + lr[j]) * CIN + lc * 8;
            cpasync16(sb + 0 * TILE2 + lr[j] * LDKB2 + lc * 16, Ahi + arow);
            cpasync16(sb + 1 * TILE2 + lr[j] * LDKB2 + lc * 16, Alo + arow);
        }
        cpasync_commit();
        float4 x0[4];
        #pragma unroll
        for (int j = 0; j < 4; j++)
            x0[j] = *(const float4*)(xg + (size_t)xrow[j] * NPIX + pixbase + xc4 * 4);
        #pragma unroll
        for (int j = 0; j < 4; j++)
            stconv4(smc + 2 * TILE2, smc + 3 * TILE2, xc4 * 4, xrow[j], x0[j]);
    }

    for (int ch = 0; ch < NCH; ch++) {
        cpasync_wait<0>();
        __syncthreads();          // chunk ch visible; all warps done compute(ch-1)

        float4 xn[4];
        const bool more = (ch + 1 < NCH);
        if (more) {
            const uint32_t nb = sb + ((ch + 1) & 1) * BUFSET;
            const int kc1 = (ch + 1) * 32;
            #pragma unroll
            for (int j = 0; j < 2; j++) {
                const size_t arow = (size_t)(bmh * 128 + lr[j]) * CIN + kc1 + lc * 8;
                cpasync16(nb + 0 * TILE2 + lr[j] * LDKB2 + lc * 16, Ahi + arow);
                cpasync16(nb + 1 * TILE2 + lr[j] * LDKB2 + lc * 16, Alo + arow);
            }
            cpasync_commit();
            #pragma unroll
            for (int j = 0; j < 4; j++)
                xn[j] = *(const float4*)(xg + (size_t)(kc1 + xrow[j]) * NPIX + pixbase + xc4 * 4);
        }

        // ---- compute chunk ch ----
        const uint32_t cb = sb + (ch & 1) * BUFSET;
        const uint32_t bAh = cb, bAl = cb + TILE2, bBh = cb + 2 * TILE2, bBl = cb + 3 * TILE2;
        #pragma unroll
        for (int ks = 0; ks < 2; ks++) {
            const int kc = ks * 16;
            uint32_t a[4][4], bh[4][2], bl[4][2];
            #pragma unroll
            for (int mt = 0; mt < 4; mt++)
                ldsm4(a[mt], bAh + (wm * 64 + mt * 16 + am_) * LDKB2 + (kc + ak_) * 2);
            #pragma unroll
            for (int pr = 0; pr < 2; pr++) {
                uint32_t r4[4];
                ldsm4(r4, bBh + (wn * 32 + pr * 16 + bn_) * LDKB2 + (kc + bk_) * 2);
                bh[2 * pr][0] = r4[0]; bh[2 * pr][1] = r4[1];
                bh[2 * pr + 1][0] = r4[2]; bh[2 * pr + 1][1] = r4[3];
            }
            #pragma unroll
            for (int mt = 0; mt < 4; mt++)
                #pragma unroll
                for (int nt = 0; nt < 4; nt++) mma16816(acc[mt][nt], a[mt], bh[nt]);
            #pragma unroll
            for (int pr = 0; pr < 2; pr++) {
                uint32_t r4[4];
                ldsm4(r4, bBl + (wn * 32 + pr * 16 + bn_) * LDKB2 + (kc + bk_) * 2);
                bl[2 * pr][0] = r4[0]; bl[2 * pr][1] = r4[1];
                bl[2 * pr + 1][0] = r4[2]; bl[2 * pr + 1][1] = r4[3];
            }
            #pragma unroll
            for (int mt = 0; mt < 4; mt++)
                #pragma unroll
                for (int nt = 0; nt < 4; nt++) mma16816(acc[mt][nt], a[mt], bl[nt]);
            #pragma unroll
            for (int mt = 0; mt < 4; mt++)
                ldsm4(a[mt], bAl + (wm * 64 + mt * 16 + am_) * LDKB2 + (kc + ak_) * 2);
            #pragma unroll
            for (int mt = 0; mt < 4; mt++)
                #pragma unroll
                for (int nt = 0; nt < 4; nt++) mma16816(acc[mt][nt], a[mt], bh[nt]);
        }

        if (more) {
            char* nbp = smc + ((ch + 1) & 1) * BUFSET;
            #pragma unroll
            for (int j = 0; j < 4; j++)
                stconv4(nbp + 2 * TILE2, nbp + 3 * TILE2, xc4 * 4, xrow[j], xn[j]);
        }
    }
    __syncthreads();   // all compute done before stage overlays buffers

    // ==================== epilogues ====================
    if (wsel >= 1) {
        const int x0 = (pixbase & 255) + wn * 32;
        const int y0 = pixbase >> 8;
        const int patch = ((y0 >> 5) << 3) + (x0 >> 5);
        const float inv = 1.f / 1024.f;
        const float* gg = p.gg[wsel];
        const float* bb = p.bb[wsel];
        const float* mm = p.mm[wsel];
        const float* vv = p.vv[wsel];
        float* outp = (wsel == 1) ? kpo : vpo;
        #pragma unroll
        for (int mt = 0; mt < 4; mt++) {
            #pragma unroll
            for (int hf = 0; hf < 2; hf++) {
                const int o = bmh * 128 + wm * 64 + mt * 16 + (lane >> 2) + hf * 8;
                const float s_r = gg[o] * rsqrtf(vv[o] + EPS);
                const float t_r = bb[o] - mm[o] * s_r;
                float s = 0.f;
                #pragma unroll
                for (int nt = 0; nt < 4; nt++) {
                    s += fmaxf(acc[mt][nt][2 * hf + 0] * s_r + t_r, 0.f);
                    s += fmaxf(acc[mt][nt][2 * hf + 1] * s_r + t_r, 0.f);
                }
                s += __shfl_xor_sync(0xffffffffu, s, 1);
                s += __shfl_xor_sync(0xffffffffu, s, 2);
                if ((lane & 3) == 0) {
                    if (wsel == 1) atomicAdd(outp + o * NUM + patch, s * inv);
                    else           atomicAdd(outp + patch * HALF + o, s * inv);
                }
            }
        }
    } else {
        // q: BN + ReLU + qscale, emit bf16 hi/lo [pix][256]
        float* stage = (float*)smc;                  // 128 x 131 fp32
        float* scb = (float*)(smc + 68608);
        float* bob = (float*)(smc + 69632);
        if (tid < 128) {
            const int o = bmh * 128 + tid;
            const float s_r = p.gg[0][o] * rsqrtf(p.vv[0][o] + EPS);
            scb[tid] = s_r;
            bob[tid] = p.bb[0][o] - p.mm[0][o] * s_r;
        }
        __syncthreads();
        #pragma unroll
        for (int mt = 0; mt < 4; mt++) {
            const int r_lo = wm * 64 + mt * 16 + (lane >> 2);
            #pragma unroll
            for (int nt = 0; nt < 4; nt++) {
                const int c = wn * 32 + nt * 8 + (lane & 3) * 2;
                stage[r_lo * 131 + c]     = fmaxf(acc[mt][nt][0] * scb[r_lo] + bob[r_lo], 0.f) * qscale;
                stage[r_lo * 131 + c + 1] = fmaxf(acc[mt][nt][1] * scb[r_lo] + bob[r_lo], 0.f) * qscale;
                stage[(r_lo + 8) * 131 + c]     = fmaxf(acc[mt][nt][2] * scb[r_lo + 8] + bob[r_lo + 8], 0.f) * qscale;
                stage[(r_lo + 8) * 131 + c + 1] = fmaxf(acc[mt][nt][3] * scb[r_lo + 8] + bob[r_lo + 8], 0.f) * qscale;
            }
        }
        __syncthreads();
        for (int i = tid; i < 128 * 64; i += 256) {
            const int pixl = i >> 6;
            const int cp = (i & 63) * 2;
            float v0 = stage[cp * 131 + pixl];
            float v1 = stage[(cp + 1) * 131 + pixl];
            __nv_bfloat16 h0 = __float2bfloat16(v0);
            __nv_bfloat16 h1 = __float2bfloat16(v1);
            const size_t off = (size_t)(pixbase + pixl) * HALF + bmh * 128 + cp;
            *(uint32_t*)(qhi + off) = packbf2(v0, v1);
            *(uint32_t*)(qlo + off) = packbf2(v0 - __bfloat162float(h0), v1 - __bfloat162float(h1));
        }
    }
}

// ==================== HMMA o-projection (grid = (4, 512)), single-barrier pipeline ====================
template <int KDIM>
__global__ void __launch_bounds__(256, 2)
proj_o(const __nv_bfloat16* __restrict__ Ahi, const __nv_bfloat16* __restrict__ Alo,
       const __nv_bfloat16* __restrict__ Bhi, const __nv_bfloat16* __restrict__ Blo,
       const float* __restrict__ gg, const float* __restrict__ bb,
       const float* __restrict__ mm, const float* __restrict__ vv,
       float* __restrict__ outp, const float* __restrict__ resid)
{
    extern __shared__ char smc[];
    const uint32_t sb = smem_to_u32(smc);

    const int tid = threadIdx.x;
    const int wid = tid >> 5;
    const int lane = tid & 31;
    const int wm = wid & 1;
    const int wn = wid >> 1;
    const int bm = blockIdx.x;            // fast -> L2 reuse of B
    const int pixbase = blockIdx.y * 128;

    float acc[4][4][4];
    #pragma unroll
    for (int mt = 0; mt < 4; mt++)
        #pragma unroll
        for (int nt = 0; nt < 4; nt++)
            #pragma unroll
            for (int e = 0; e < 4; e++) acc[mt][nt][e] = 0.f;

    const int am_ = lane & 15;
    const int ak_ = (lane >> 4) * 8;
    const int bn_ = (lane & 7) + ((lane >> 4) << 3);
    const int bk_ = ((lane >> 3) & 1) * 8;

    const int lr[2] = { tid >> 2, (tid + 256) >> 2 };
    const int lc = tid & 3;

    const int NCH = KDIM / 32;

    {
        #pragma unroll
        for (int j = 0; j < 2; j++) {
            const int r = lr[j];
            const size_t arow = (size_t)(bm * 128 + r) * KDIM + lc * 8;
            const size_t brow = (size_t)(pixbase + r) * KDIM + lc * 8;
            cpasync16(sb + 0 * TILE2 + r * LDKB2 + lc * 16, Ahi + arow);
            cpasync16(sb + 1 * TILE2 + r * LDKB2 + lc * 16, Alo + arow);
            cpasync16(sb + 2 * TILE2 + r * LDKB2 + lc * 16, Bhi + brow);
            cpasync16(sb + 3 * TILE2 + r * LDKB2 + lc * 16, Blo + brow);
        }
        cpasync_commit();
    }

    for (int ch = 0; ch < NCH; ch++) {
        cpasync_wait<0>();
        __syncthreads();
        if (ch + 1 < NCH) {
            const uint32_t bufb = sb + ((ch + 1) & 1) * BUFSET;
            const int kc1 = (ch + 1) * 32;
            #pragma unroll
            for (int j = 0; j < 2; j++) {
                const int r = lr[j];
                const size_t arow = (size_t)(bm * 128 + r) * KDIM + kc1 + lc * 8;
                const size_t brow = (size_t)(pixbase + r) * KDIM + kc1 + lc * 8;
                cpasync16(bufb + 0 * TILE2 + r * LDKB2 + lc * 16, Ahi + arow);
                cpasync16(bufb + 1 * TILE2 + r * LDKB2 + lc * 16, Alo + arow);
                cpasync16(bufb + 2 * TILE2 + r * LDKB2 + lc * 16, Bhi + brow);
                cpasync16(bufb + 3 * TILE2 + r * LDKB2 + lc * 16, Blo + brow);
            }
            cpasync_commit();
        }

        const uint32_t cb = sb + (ch & 1) * BUFSET;
        const uint32_t bAh = cb, bAl = cb + TILE2, bBh = cb + 2 * TILE2, bBl = cb + 3 * TILE2;
        #pragma unroll
        for (int ks = 0; ks < 2; ks++) {
            const int kc = ks * 16;
            uint32_t a[4][4], bh[4][2], bl[4][2];
            #pragma unroll
            for (int mt = 0; mt < 4; mt++)
                ldsm4(a[mt], bAh + (wm * 64 + mt * 16 + am_) * LDKB2 + (kc + ak_) * 2);
            #pragma unroll
            for (int pr = 0; pr < 2; pr++) {
                uint32_t r4[4];
                ldsm4(r4, bBh + (wn * 32 + pr * 16 + bn_) * LDKB2 + (kc + bk_) * 2);
                bh[2 * pr][0] = r4[0]; bh[2 * pr][1] = r4[1];
                bh[2 * pr + 1][0] = r4[2]; bh[2 * pr + 1][1] = r4[3];
            }
            #pragma unroll
            for (int mt = 0; mt < 4; mt++)
                #pragma unroll
                for (int nt = 0; nt < 4; nt++) mma16816(acc[mt][nt], a[mt], bh[nt]);
            #pragma unroll
            for (int pr = 0; pr < 2; pr++) {
                uint32_t r4[4];
                ldsm4(r4, bBl + (wn * 32 + pr * 16 + bn_) * LDKB2 + (kc + bk_) * 2);
                bl[2 * pr][0] = r4[0]; bl[2 * pr][1] = r4[1];
                bl[2 * pr + 1][0] = r4[2]; bl[2 * pr + 1][1] = r4[3];
            }
            #pragma unroll
            for (int mt = 0; mt < 4; mt++)
                #pragma unroll
                for (int nt = 0; nt < 4; nt++) mma16816(acc[mt][nt], a[mt], bl[nt]);
            #pragma unroll
            for (int mt = 0; mt < 4; mt++)
                ldsm4(a[mt], bAl + (wm * 64 + mt * 16 + am_) * LDKB2 + (kc + ak_) * 2);
            #pragma unroll
            for (int mt = 0; mt < 4; mt++)
                #pragma unroll
                for (int nt = 0; nt < 4; nt++) mma16816(acc[mt][nt], a[mt], bh[nt]);
        }
    }
    __syncthreads();

    float* stage = (float*)smc;
    float* scb = (float*)(smc + 68608);
    float* bob = (float*)(smc + 69632);
    if (tid < 128) {
        const int o = bm * 128 + tid;
        const float s_r = gg[o] * rsqrtf(vv[o] + EPS);
        scb[tid] = s_r;
        bob[tid] = bb[o] - mm[o] * s_r;
    }
    __syncthreads();
    #pragma unroll
    for (int mt = 0; mt < 4; mt++) {
        const int r_lo = wm * 64 + mt * 16 + (lane >> 2);
        #pragma unroll
        for (int nt = 0; nt < 4; nt++) {
            const int c = wn * 32 + nt * 8 + (lane & 3) * 2;
            stage[r_lo * 130 + c]     = fmaxf(acc[mt][nt][0] * scb[r_lo] + bob[r_lo], 0.f);
            stage[r_lo * 130 + c + 1] = fmaxf(acc[mt][nt][1] * scb[r_lo] + bob[r_lo], 0.f);
            stage[(r_lo + 8) * 130 + c]     = fmaxf(acc[mt][nt][2] * scb[r_lo + 8] + bob[r_lo + 8], 0.f);
            stage[(r_lo + 8) * 130 + c + 1] = fmaxf(acc[mt][nt][3] * scb[r_lo + 8] + bob[r_lo + 8], 0.f);
        }
    }
    __syncthreads();
    for (int i = tid; i < 128 * 128; i += 256) {
        const int r = i >> 7;
        const int c = i & 127;
        const size_t go = (size_t)(bm * 128 + r) * NPIX + pixbase + c;
        outp[go] = stage[r * 130 + c] + resid[go];
    }
}

// ==================== attn via mma.sync, single-barrier pipeline ====================
#define AT_KPH 0
#define AT_KPSTR 528
#define AT_KPL (64 * AT_KPSTR)          // 33792
#define AT_QB  (2 * 64 * AT_KPSTR)      // 67584; two buffers of 2*10240
#define AT_QBSZ (2 * 128 * LDKB2)       // 20480
#define AT_SMEM (AT_QB + 2 * AT_QBSZ)   // 108544
__global__ void __launch_bounds__(256, 2)
attn_mma(const __nv_bfloat16* __restrict__ qhi, const __nv_bfloat16* __restrict__ qlo,
         const __nv_bfloat16* __restrict__ kph, const __nv_bfloat16* __restrict__ kpl,
         __nv_bfloat16* __restrict__ ahi, __nv_bfloat16* __restrict__ alo)
{
    extern __shared__ char smc[];
    const uint32_t sb = smem_to_u32(smc);

    const int rowblk = blockIdx.x;
    const int b = blockIdx.y;
    const int tid = threadIdx.x;
    const int wid = tid >> 5;
    const int lane = tid & 31;
    const int ph = b >> 3, pw = b & 7;
    const int pixbase = ph * 32 * WW + pw * 32;

    #pragma unroll
    for (int j = 0; j < 8; j++) {
        const int idx = tid + j * 256;       // 0..2047
        const int r = idx >> 5;
        const int c16 = idx & 31;
        *(uint4*)(smc + AT_KPH + r * AT_KPSTR + c16 * 16) = *(const uint4*)(kph + r * HALF + c16 * 8);
        *(uint4*)(smc + AT_KPL + r * AT_KPSTR + c16 * 16) = *(const uint4*)(kpl + r * HALF + c16 * 8);
    }

    const int qr[2] = { tid >> 2, (tid + 256) >> 2 };
    const int qc = tid & 3;
    int qpix[2];
    #pragma unroll
    for (int j = 0; j < 2; j++) {
        const int n = rowblk * 128 + qr[j];
        qpix[j] = pixbase + (n >> 5) * WW + (n & 31);
    }

    {
        const uint32_t qb = sb + AT_QB;
        #pragma unroll
        for (int j = 0; j < 2; j++) {
            const size_t g = (size_t)qpix[j] * HALF + qc * 8;
            cpasync16(qb + qr[j] * LDKB2 + qc * 16, qhi + g);
            cpasync16(qb + 128 * LDKB2 + qr[j] * LDKB2 + qc * 16, qlo + g);
        }
        cpasync_commit();
    }

    const int am_ = lane & 15;
    const int ak_ = (lane >> 4) * 8;
    const int bn_ = (lane & 7) + ((lane >> 4) << 3);
    const int bk_ = ((lane >> 3) & 1) * 8;
    const int grp = lane >> 2;
    const int qd = lane & 3;

    float S[8][4];
    #pragma unroll
    for (int nt = 0; nt < 8; nt++)
        #pragma unroll
        for (int e = 0; e < 4; e++) S[nt][e] = 0.f;

    const int NCH = HALF / 32;   // 8
    for (int ch = 0; ch < NCH; ch++) {
        cpasync_wait<0>();
        __syncthreads();          // chunk ch + kp visible; compute(ch-1) done
        if (ch + 1 < NCH) {
            const uint32_t qb = sb + AT_QB + ((ch + 1) & 1) * AT_QBSZ;
            const int kc1 = (ch + 1) * 32;
            #pragma unroll
            for (int j = 0; j < 2; j++) {
                const size_t g = (size_t)qpix[j] * HALF + kc1 + qc * 8;
                cpasync16(qb + qr[j] * LDKB2 + qc * 16, qhi + g);
                cpasync16(qb + 128 * LDKB2 + qr[j] * LDKB2 + qc * 16, qlo + g);
            }
            cpasync_commit();
        }

        const uint32_t qb = sb + AT_QB + (ch & 1) * AT_QBSZ;
        const uint32_t qHI = qb, qLO = qb + 128 * LDKB2;
        #pragma unroll
        for (int ks = 0; ks < 2; ks++) {
            const int kc = ks * 16;
            const int kb = (ch * 32 + kc) * 2;
            uint32_t a[4], bh[8][2], bl[8][2];
            ldsm4(a, qHI + (wid * 16 + am_) * LDKB2 + (kc + ak_) * 2);
            #pragma unroll
            for (int pr = 0; pr < 4; pr++) {
                uint32_t r4[4];
                ldsm4(r4, sb + AT_KPH + (pr * 16 + bn_) * AT_KPSTR + kb + bk_ * 2);
                bh[2 * pr][0] = r4[0]; bh[2 * pr][1] = r4[1];
                bh[2 * pr + 1][0] = r4[2]; bh[2 * pr + 1][1] = r4[3];
            }
            #pragma unroll
            for (int nt = 0; nt < 8; nt++) mma16816(S[nt], a, bh[nt]);
            #pragma unroll
            for (int pr = 0; pr < 4; pr++) {
                uint32_t r4[4];
                ldsm4(r4, sb + AT_KPL + (pr * 16 + bn_) * AT_KPSTR + kb + bk_ * 2);
                bl[2 * pr][0] = r4[0]; bl[2 * pr][1] = r4[1];
                bl[2 * pr + 1][0] = r4[2]; bl[2 * pr + 1][1] = r4[3];
            }
            #pragma unroll
            for (int nt = 0; nt < 8; nt++) mma16816(S[nt], a, bl[nt]);
            ldsm4(a, qLO + (wid * 16 + am_) * LDKB2 + (kc + ak_) * 2);
            #pragma unroll
            for (int nt = 0; nt < 8; nt++) mma16816(S[nt], a, bh[nt]);
        }
    }

    const int r1 = wid * 16 + grp;
    #pragma unroll
    for (int nt = 0; nt < 8; nt++) {
        const int col = nt * 8 + qd * 2;
        {
            const int n = rowblk * 128 + r1;
            const size_t off = ((size_t)b * 1024 + n) * 64 + col;
            float v0 = S[nt][0], v1 = S[nt][1];
            __nv_bfloat16 h0 = __float2bfloat16(v0);
            __nv_bfloat16 h1 = __float2bfloat16(v1);
            *(uint32_t*)(ahi + off) = packbf2(v0, v1);
            *(uint32_t*)(alo + off) = packbf2(v0 - __bfloat162float(h0), v1 - __bfloat162float(h1));
        }
        {
            const int n = rowblk * 128 + r1 + 8;
            const size_t off = ((size_t)b * 1024 + n) * 64 + col;
            float v0 = S[nt][2], v1 = S[nt][3];
            __nv_bfloat16 h0 = __float2bfloat16(v0);
            __nv_bfloat16 h1 = __float2bfloat16(v1);
            *(uint32_t*)(ahi + off) = packbf2(v0, v1);
            *(uint32_t*)(alo + off) = packbf2(v0 - __bfloat162float(h0), v1 - __bfloat162float(h1));
        }
    }
}

// ==================== flash v3: mma.sync nested-softmax attention ====================
#define FLDB 144                 // bf16 tile stride bytes
#define F_QHI 0
#define F_QLO 9216
#define F_KB   18432             // K buffers: base + buf*18432; KHI at +0, KLO at +9216
#define F_REDM 55296             // float[64][4]
#define F_REDS 56320             // float[64][4]
#define F_MS   57344             // float[64]
#define F_LS   57600
#define F_SCS  57856
#define F_MNS  58112
#define F_REDF 58368             // float[64][16]
#define F_TOTAL 62464
__global__ void __launch_bounds__(256, 2)
flash3_kernel(const __nv_bfloat16* __restrict__ ahi, const __nv_bfloat16* __restrict__ alo,
              const float* __restrict__ vp,
              __nv_bfloat16* __restrict__ pthi, __nv_bfloat16* __restrict__ ptlo)
{
    extern __shared__ char smc[];
    const uint32_t sb = smem_to_u32(smc);
    float* REDM = (float*)(smc + F_REDM);
    float* REDS = (float*)(smc + F_REDS);
    float* m_s  = (float*)(smc + F_MS);
    float* l_s  = (float*)(smc + F_LS);
    float* sc_s = (float*)(smc + F_SCS);
    float* mn_s = (float*)(smc + F_MNS);
    float* REDF = (float*)(smc + F_REDF);

    const int rblk = blockIdx.x;    // 0..15
    const int b = blockIdx.y;       // patch
    const int tid = threadIdx.x;
    const int lane = tid & 31;
    const int wid = tid >> 5;
    const int wm = wid >> 2;        // 0..1
    const int wn = wid & 3;         // 0..3
    const int r0 = rblk * 64;
    const size_t abase = (size_t)b * 1024 * 64;

    if (tid < 64) { m_s[tid] = -1e30f; l_s[tid] = 0.f; }

    const int kr[2] = { tid >> 3, (tid + 256) >> 3 };
    const int kc_ = tid & 7;

    {
        const uint32_t kb = sb + F_KB;
        #pragma unroll
        for (int j = 0; j < 2; j++) {
            const int r = kr[j];
            const size_t g = abase + (size_t)r * 64 + kc_ * 8;
            cpasync16(kb + r * FLDB + kc_ * 16, ahi + g);
            cpasync16(kb + 9216 + r * FLDB + kc_ * 16, alo + g);
        }
        cpasync_commit();
    }

    {
        #pragma unroll
        for (int i = 0; i < 2; i++) {
            const int idx = tid + i * 256;
            const int r = idx >> 3;
            const int c = idx & 7;
            const size_t g = abase + (size_t)(r0 + r) * 64 + c * 8;
            *(uint4*)(smc + F_QHI + r * FLDB + c * 16) = *(const uint4*)(ahi + g);
            *(uint4*)(smc + F_QLO + r * FLDB + c * 16) = *(const uint4*)(alo + g);
        }
    }

    const int am_ = lane & 15;
    const int ak_ = (lane >> 4) * 8;
    const int bn_ = (lane & 7) + ((lane >> 4) << 3);
    const int bk_ = ((lane >> 3) & 1) * 8;
    const int vk_ = lane & 15;
    const int vn_ = (lane >> 4) << 3;
    const int grp = lane >> 2;
    const int qd  = lane & 3;

    float O[2][8][4];
    #pragma unroll
    for (int mt = 0; mt < 2; mt++)
        #pragma unroll
        for (int n8 = 0; n8 < 8; n8++)
            #pragma unroll
            for (int e = 0; e < 4; e++) O[mt][n8][e] = 0.f;

    for (int t = 0; t < 16; t++) {
        cpasync_wait<0>();
        __syncthreads();          // tile t + Q visible; GEMM2(t-1) + REDS(t-1) done
        if (t > 0 && tid < 64) {
            l_s[tid] = l_s[tid] * sc_s[tid]
                     + REDS[tid * 4 + 0] + REDS[tid * 4 + 1]
                     + REDS[tid * 4 + 2] + REDS[tid * 4 + 3];
        }
        if (t + 1 < 16) {
            const uint32_t kb = sb + F_KB + ((t + 1) & 1) * 18432;
            #pragma unroll
            for (int j = 0; j < 2; j++) {
                const int r = kr[j];
                const size_t g = abase + (size_t)((t + 1) * 64 + r) * 64 + kc_ * 8;
                cpasync16(kb + r * FLDB + kc_ * 16, ahi + g);
                cpasync16(kb + 9216 + r * FLDB + kc_ * 16, alo + g);
            }
            cpasync_commit();
        }

        const uint32_t kb = sb + F_KB + (t & 1) * 18432;
        const uint32_t kHI = kb, kLO = kb + 9216;

        float S[2][2][4];
        #pragma unroll
        for (int mt = 0; mt < 2; mt++)
            #pragma unroll
            for (int nt = 0; nt < 2; nt++)
                #pragma unroll
                for (int e = 0; e < 4; e++) S[mt][nt][e] = 0.f;
        #pragma unroll
        for (int ks = 0; ks < 4; ks++) {
            const int kc = ks * 16;
            uint32_t a[2][4], bh[2][2], bl[2][2];
            #pragma unroll
            for (int mt = 0; mt < 2; mt++)
                ldsm4(a[mt], sb + F_QHI + (wm * 32 + mt * 16 + am_) * FLDB + (kc + ak_) * 2);
            {
                uint32_t r4[4];
                ldsm4(r4, kHI + (wn * 16 + bn_) * FLDB + (kc + bk_) * 2);
                bh[0][0] = r4[0]; bh[0][1] = r4[1]; bh[1][0] = r4[2]; bh[1][1] = r4[3];
            }
            #pragma unroll
            for (int mt = 0; mt < 2; mt++)
                #pragma unroll
                for (int nt = 0; nt < 2; nt++) mma16816(S[mt][nt], a[mt], bh[nt]);
            {
                uint32_t r4[4];
                ldsm4(r4, kLO + (wn * 16 + bn_) * FLDB + (kc + bk_) * 2);
                bl[0][0] = r4[0]; bl[0][1] = r4[1]; bl[1][0] = r4[2]; bl[1][1] = r4[3];
            }
            #pragma unroll
            for (int mt = 0; mt < 2; mt++)
                #pragma unroll
                for (int nt = 0; nt < 2; nt++) mma16816(S[mt][nt], a[mt], bl[nt]);
            #pragma unroll
            for (int mt = 0; mt < 2; mt++)
                ldsm4(a[mt], sb + F_QLO + (wm * 32 + mt * 16 + am_) * FLDB + (kc + ak_) * 2);
            #pragma unroll
            for (int mt = 0; mt < 2; mt++)
                #pragma unroll
                for (int nt = 0; nt < 2; nt++) mma16816(S[mt][nt], a[mt], bh[nt]);
        }

        #pragma unroll
        for (int mt = 0; mt < 2; mt++) {
            float la = fmaxf(fmaxf(S[mt][0][0], S[mt][0][1]), fmaxf(S[mt][1][0], S[mt][1][1]));
            float lb = fmaxf(fmaxf(S[mt][0][2], S[mt][0][3]), fmaxf(S[mt][1][2], S[mt][1][3]));
            la = fmaxf(la, __shfl_xor_sync(0xffffffffu, la, 1));
            la = fmaxf(la, __shfl_xor_sync(0xffffffffu, la, 2));
            lb = fmaxf(lb, __shfl_xor_sync(0xffffffffu, lb, 1));
            lb = fmaxf(lb, __shfl_xor_sync(0xffffffffu, lb, 2));
            if (qd == 0) {
                const int r1 = wm * 32 + mt * 16 + grp;
                REDM[r1 * 4 + wn] = la;
                REDM[(r1 + 8) * 4 + wn] = lb;
            }
        }
        __syncthreads();
        if (tid < 64) {
            float mt_ = fmaxf(fmaxf(REDM[tid * 4], REDM[tid * 4 + 1]),
                              fmaxf(REDM[tid * 4 + 2], REDM[tid * 4 + 3]));
            const float mo = m_s[tid];
            const float mn = fmaxf(mo, mt_);
            sc_s[tid] = __expf(mo - mn);
            mn_s[tid] = mn;
            m_s[tid] = mn;
        }
        __syncthreads();

        uint32_t aPh[2][4], aPl[2][4];
        #pragma unroll
        for (int mt = 0; mt < 2; mt++) {
            const int r1 = wm * 32 + mt * 16 + grp;
            const float mna = mn_s[r1];
            const float mnb = mn_s[r1 + 8];
            float P[2][4];
            #pragma unroll
            for (int nt = 0; nt < 2; nt++) {
                P[nt][0] = __expf(S[mt][nt][0] - mna);
                P[nt][1] = __expf(S[mt][nt][1] - mna);
                P[nt][2] = __expf(S[mt][nt][2] - mnb);
                P[nt][3] = __expf(S[mt][nt][3] - mnb);
            }
            float ra = P[0][0] + P[0][1] + P[1][0] + P[1][1];
            float rb = P[0][2] + P[0][3] + P[1][2] + P[1][3];
            ra += __shfl_xor_sync(0xffffffffu, ra, 1);
            ra += __shfl_xor_sync(0xffffffffu, ra, 2);
            rb += __shfl_xor_sync(0xffffffffu, rb, 1);
            rb += __shfl_xor_sync(0xffffffffu, rb, 2);
            if (qd == 0) {
                REDS[r1 * 4 + wn] = ra;
                REDS[(r1 + 8) * 4 + wn] = rb;
            }
            aPh[mt][0] = packbf2(P[0][0], P[0][1]);
            aPh[mt][1] = packbf2(P[0][2], P[0][3]);
            aPh[mt][2] = packbf2(P[1][0], P[1][1]);
            aPh[mt][3] = packbf2(P[1][2], P[1][3]);
            float l00 = P[0][0] - __bfloat162float(__float2bfloat16(P[0][0]));
            float l01 = P[0][1] - __bfloat162float(__float2bfloat16(P[0][1]));
            float l02 = P[0][2] - __bfloat162float(__float2bfloat16(P[0][2]));
            float l03 = P[0][3] - __bfloat162float(__float2bfloat16(P[0][3]));
            float l10 = P[1][0] - __bfloat162float(__float2bfloat16(P[1][0]));
            float l11 = P[1][1] - __bfloat162float(__float2bfloat16(P[1][1]));
            float l12 = P[1][2] - __bfloat162float(__float2bfloat16(P[1][2]));
            float l13 = P[1][3] - __bfloat162float(__float2bfloat16(P[1][3]));
            aPl[mt][0] = packbf2(l00, l01);
            aPl[mt][1] = packbf2(l02, l03);
            aPl[mt][2] = packbf2(l10, l11);
            aPl[mt][3] = packbf2(l12, l13);
            const float sa = sc_s[r1];
            const float sbx = sc_s[r1 + 8];
            #pragma unroll
            for (int n8 = 0; n8 < 8; n8++) {
                O[mt][n8][0] *= sa; O[mt][n8][1] *= sa;
                O[mt][n8][2] *= sbx; O[mt][n8][3] *= sbx;
            }
        }

        #pragma unroll
        for (int g = 0; g < 4; g++) {
            const int n0 = g * 16;
            uint32_t vh[4], vl[4];
            ldsm4t(vh, kHI + (wn * 16 + vk_) * FLDB + (n0 + vn_) * 2);
            ldsm4t(vl, kLO + (wn * 16 + vk_) * FLDB + (n0 + vn_) * 2);
            uint32_t b0h[2] = { vh[0], vh[1] }, b1h[2] = { vh[2], vh[3] };
            uint32_t b0l[2] = { vl[0], vl[1] }, b1l[2] = { vl[2], vl[3] };
            #pragma unroll
            for (int mt = 0; mt < 2; mt++) {
                mma16816(O[mt][2 * g + 0], aPh[mt], b0h);
                mma16816(O[mt][2 * g + 1], aPh[mt], b1h);
                mma16816(O[mt][2 * g + 0], aPh[mt], b0l);
                mma16816(O[mt][2 * g + 1], aPh[mt], b1l);
                mma16816(O[mt][2 * g + 0], aPl[mt], b0h);
                mma16816(O[mt][2 * g + 1], aPl[mt], b1h);
            }
        }
    }
    __syncthreads();
    if (tid < 64) {
        l_s[tid] = l_s[tid] * sc_s[tid]
                 + REDS[tid * 4 + 0] + REDS[tid * 4 + 1]
                 + REDS[tid * 4 + 2] + REDS[tid * 4 + 3];
    }

    float* Os = (float*)(smc + 0);          // [64][66]
    for (int i = tid; i < 64 * 66; i += 256) Os[i] = 0.f;
    __syncthreads();
    #pragma unroll 1
    for (int p = 0; p < 4; p++) {
        if (wn == p) {
            #pragma unroll
            for (int mt = 0; mt < 2; mt++) {
                const int r1 = wm * 32 + mt * 16 + grp;
                #pragma unroll
                for (int n8 = 0; n8 < 8; n8++) {
                    const int c = n8 * 8 + qd * 2;
                    Os[r1 * 66 + c]       += O[mt][n8][0];
                    Os[r1 * 66 + c + 1]   += O[mt][n8][1];
                    Os[(r1 + 8) * 66 + c]     += O[mt][n8][2];
                    Os[(r1 + 8) * 66 + c + 1] += O[mt][n8][3];
                }
            }
        }
        __syncthreads();
    }

    const int txx = tid & 15;
    const int tyy = tid >> 4;
    float fv[4][4];
    #pragma unroll
    for (int i = 0; i < 4; i++) {
        const int rr = tyy * 4 + i;
        const float linv = 1.f / l_s[rr];
        const size_t goff = abase + (size_t)(r0 + rr) * 64 + txx * 4;
        uint2 uh = *(const uint2*)(ahi + goff);
        uint2 ul = *(const uint2*)(alo + goff);
        __nv_bfloat162 h0 = *(__nv_bfloat162*)&uh.x;
        __nv_bfloat162 h1 = *(__nv_bfloat162*)&uh.y;
        __nv_bfloat162 l0 = *(__nv_bfloat162*)&ul.x;
        __nv_bfloat162 l1 = *(__nv_bfloat162*)&ul.y;
        fv[i][0] = __bfloat162float(h0.x) + __bfloat162float(l0.x) + Os[rr * 66 + txx * 4 + 0] * linv;
        fv[i][1] = __bfloat162float(h0.y) + __bfloat162float(l0.y) + Os[rr * 66 + txx * 4 + 1] * linv;
        fv[i][2] = __bfloat162float(h1.x) + __bfloat162float(l1.x) + Os[rr * 66 + txx * 4 + 2] * linv;
        fv[i][3] = __bfloat162float(h1.y) + __bfloat162float(l1.y) + Os[rr * 66 + txx * 4 + 3] * linv;
    }
    #pragma unroll
    for (int i = 0; i < 4; i++) {
        float lm = fmaxf(fmaxf(fv[i][0], fv[i][1]), fmaxf(fv[i][2], fv[i][3]));
        REDF[(tyy * 4 + i) * 16 + txx] = lm;
    }
    __syncthreads();
    if (tid < 64) {
        float mt_ = REDF[tid * 16];
        #pragma unroll
        for (int j = 1; j < 16; j++) mt_ = fmaxf(mt_, REDF[tid * 16 + j]);
        mn_s[tid] = mt_;
    }
    __syncthreads();
    #pragma unroll
    for (int i = 0; i < 4; i++) {
        const int rr = tyy * 4 + i;
        const float mn = mn_s[rr];
        float rs = 0.f;
        #pragma unroll
        for (int j = 0; j < 4; j++) { fv[i][j] = __expf(fv[i][j] - mn); rs += fv[i][j]; }
        REDF[rr * 16 + txx] = rs;
    }
    __syncthreads();
    if (tid < 64) {
        float su = REDF[tid * 16];
        #pragma unroll
        for (int j = 1; j < 16; j++) su += REDF[tid * 16 + j];
        l_s[tid] = 1.f / su;
    }
    __syncthreads();
    float* Ps = (float*)(smc + F_KB);       // [64][68] overlay on K buf0
    #pragma unroll
    for (int i = 0; i < 4; i++) {
        const int rr = tyy * 4 + i;
        const float inv = l_s[rr];
        *(float4*)&Ps[rr * 68 + txx * 4] =
            make_float4(fv[i][0] * inv, fv[i][1] * inv, fv[i][2] * inv, fv[i][3] * inv);
    }
    __syncthreads();

    float acc[4][16];
    #pragma unroll
    for (int i = 0; i < 4; i++)
        #pragma unroll
        for (int j = 0; j < 16; j++) acc[i][j] = 0.f;
    #pragma unroll 2
    for (int m = 0; m < 64; m++) {
        float pr[4];
        #pragma unroll
        for (int i = 0; i < 4; i++) pr[i] = Ps[(tyy * 4 + i) * 68 + m];
        const float4* vr = (const float4*)(vp + m * 256 + txx * 16);
        float4 v0 = vr[0], v1 = vr[1], v2 = vr[2], v3 = vr[3];
        const float vw[16] = {v0.x, v0.y, v0.z, v0.w, v1.x, v1.y, v1.z, v1.w,
                              v2.x, v2.y, v2.z, v2.w, v3.x, v3.y, v3.z, v3.w};
        #pragma unroll
        for (int i = 0; i < 4; i++)
            #pragma unroll
            for (int j = 0; j < 16; j++) acc[i][j] += pr[i] * vw[j];
    }

    const int ph = b >> 3, pw = b & 7;
    const int pixbase = ph * 32 * WW + pw * 32;
    float* stg = (float*)(smc + 0);
    #pragma unroll 1
    for (int g = 0; g < 4; g++) {
        __syncthreads();
        if ((txx >> 2) == g) {
            const int txl = txx & 3;
            #pragma unroll
            for (int i = 0; i < 4; i++)
                #pragma unroll
                for (int j = 0; j < 16; j++)
                    stg[(tyy * 4 + i) * 65 + txl * 16 + j] = acc[i][j];
        }
        __syncthreads();
        const int rl = tid >> 2;
        const int cc0 = (tid & 3) * 16;
        const int n = r0 + rl;
        const int pix = pixbase + (n >> 5) * WW + (n & 31);
        #pragma unroll
        for (int k2 = 0; k2 < 16; k2++) {
            float v = stg[rl * 65 + cc0 + k2];
            __nv_bfloat16 h = __float2bfloat16(v);
            const size_t off = (size_t)pix * HALF + g * 64 + cc0 + k2;
            pthi[off] = h;
            ptlo[off] = __float2bfloat16(v - __bfloat162float(h));
        }
    }
}

// ==================== launch ====================
extern "C" void kernel_launch(void* const* d_in, const int* in_sizes, int n_in,
                              void* d_out, int out_size)
{
    const float* x   = (const float*)d_in[0];
    const float* q_w = (const float*)d_in[1];
    const float* q_g = (const float*)d_in[2];
    const float* q_b = (const float*)d_in[3];
    const float* q_m = (const float*)d_in[4];
    const float* q_v = (const float*)d_in[5];
    const float* k_w = (const float*)d_in[6];
    const float* k_g = (const float*)d_in[7];
    const float* k_b = (const float*)d_in[8];
    const float* k_m = (const float*)d_in[9];
    const float* k_v = (const float*)d_in[10];
    const float* v_w = (const float*)d_in[11];
    const float* v_g = (const float*)d_in[12];
    const float* v_b = (const float*)d_in[13];
    const float* v_m = (const float*)d_in[14];
    const float* v_v = (const float*)d_in[15];
    const float* o_w = (const float*)d_in[16];
    const float* o_g = (const float*)d_in[17];
    const float* o_b = (const float*)d_in[18];
    const float* o_m = (const float*)d_in[19];
    const float* o_v = (const float*)d_in[20];
    float* out = (float*)d_out;

    __nv_bfloat16 *qthi, *qtlo, *pthi, *ptlo, *ahi, *alo, *kpbh, *kpbl;
    __nv_bfloat16 (*whi)[CIN * HALF], (*wlo)[CIN * HALF];
    float *gkp, *gvp;
    cudaGetSymbolAddress((void**)&qthi, g_qthi);
    cudaGetSymbolAddress((void**)&qtlo, g_qtlo);
    cudaGetSymbolAddress((void**)&pthi, g_pthi);
    cudaGetSymbolAddress((void**)&ptlo, g_ptlo);
    cudaGetSymbolAddress((void**)&ahi, g_ahi);
    cudaGetSymbolAddress((void**)&alo, g_alo);
    cudaGetSymbolAddress((void**)&kpbh, g_kpbh);
    cudaGetSymbolAddress((void**)&kpbl, g_kpbl);
    cudaGetSymbolAddress((void**)&whi, g_whi);
    cudaGetSymbolAddress((void**)&wlo, g_wlo);
    cudaGetSymbolAddress((void**)&gkp, g_kp);
    cudaGetSymbolAddress((void**)&gvp, g_vp);

    const float qscale = 0.044194173824159216f;   // 512^-0.5

    // conversions (x transpose/convert now fused into proj_qkv)
    conv_w4_kernel<<<dim3(512, 4), 256>>>(q_w, k_w, v_w, o_w, (__nv_bfloat16*)whi, (__nv_bfloat16*)wlo);
    zero_pool_kernel<<<64, 256>>>(gkp, gvp);

    // fused q/k/v projections (proj-slice fast -> L2 reuse of x tiles)
    QKVParams p;
    p.whi[0] = whi[0]; p.whi[1] = whi[1]; p.whi[2] = whi[2];
    p.wlo[0] = wlo[0]; p.wlo[1] = wlo[1]; p.wlo[2] = wlo[2];
    p.gg[0] = q_g; p.gg[1] = k_g; p.gg[2] = v_g;
    p.bb[0] = q_b; p.bb[1] = k_b; p.bb[2] = v_b;
    p.mm[0] = q_m; p.mm[1] = k_m; p.mm[2] = v_m;
    p.vv[0] = q_v; p.vv[1] = k_v; p.vv[2] = v_v;

    cudaFuncSetAttribute(proj_qkv, cudaFuncAttributeMaxDynamicSharedMemorySize, PROJ_SMEM);
    proj_qkv<<<dim3(6, NPIX / 128), 256, PROJ_SMEM>>>(
        p, x, qthi, qtlo, gkp, gvp, qscale);

    // kp -> bf16 [patch][c]
    kconv_kernel<<<64, 256>>>(gkp, kpbh, kpbl);

    // attn via mma.sync
    cudaFuncSetAttribute(attn_mma, cudaFuncAttributeMaxDynamicSharedMemorySize, AT_SMEM);
    attn_mma<<<dim3(8, NUM), 256, AT_SMEM>>>(qthi, qtlo, kpbh, kpbl, ahi, alo);

    // flash v3
    cudaFuncSetAttribute(flash3_kernel, cudaFuncAttributeMaxDynamicSharedMemorySize, F_TOTAL);
    flash3_kernel<<<dim3(16, NUM), 256, F_TOTAL>>>(ahi, alo, gvp, pthi, ptlo);

    // o projection + residual -> d_out (bm fast -> L2 reuse of pthi/ptlo tiles)
    cudaFuncSetAttribute(proj_o<HALF>, cudaFuncAttributeMaxDynamicSharedMemorySize, PROJ_SMEM);
    proj_o<HALF><<<dim3(CIN / 128, NPIX / 128), 256, PROJ_SMEM>>>(
        whi[3], wlo[3], pthi, ptlo, o_g, o_b, o_m, o_v, out, x);
}

// round 15
// speedup vs baseline: 1.4819x; 1.4819x over previous
#include <cuda_runtime.h>
#include <cuda_bf16.h>
#include <cstdint>
#include <math.h>

#define HH 256
#define WW 256
#define NPIX 65536          // H*W
#define CIN 512
#define HALF 256
#define PSZ 32
#define NH 8
#define NUM 64              // patches
#define EPS 1e-5f

// ==================== mma.sync / ldmatrix / cp.async helpers ====================
__device__ __forceinline__ uint32_t smem_to_u32(const void* smem_ptr) {
    uint32_t addr;
    asm("{ .reg .u64 tmp; cvta.to.shared.u64 tmp, %1; cvt.u32.u64 %0, tmp; }"
        : "=r"(addr) : "l"(smem_ptr));
    return addr;
}
__device__ __forceinline__ void ldsm4(uint32_t* r, uint32_t addr) {
    asm volatile("ldmatrix.sync.aligned.m8n8.x4.shared.b16 {%0,%1,%2,%3}, [%4];"
        : "=r"(r[0]), "=r"(r[1]), "=r"(r[2]), "=r"(r[3]) : "r"(addr));
}
__device__ __forceinline__ void ldsm4t(uint32_t* r, uint32_t addr) {
    asm volatile("ldmatrix.sync.aligned.m8n8.x4.trans.shared.b16 {%0,%1,%2,%3}, [%4];"
        : "=r"(r[0]), "=r"(r[1]), "=r"(r[2]), "=r"(r[3]) : "r"(addr));
}
__device__ __forceinline__ void mma16816(float* c, const uint32_t* a, const uint32_t* b) {
    asm volatile(
        "mma.sync.aligned.m16n8k16.row.col.f32.bf16.bf16.f32 "
        "{%0,%1,%2,%3}, {%4,%5,%6,%7}, {%8,%9}, {%0,%1,%2,%3};"
        : "+f"(c[0]), "+f"(c[1]), "+f"(c[2]), "+f"(c[3])
        : "r"(a[0]), "r"(a[1]), "r"(a[2]), "r"(a[3]), "r"(b[0]), "r"(b[1]));
}
__device__ __forceinline__ uint32_t packbf2(float lo, float hi) {
    __nv_bfloat162 h = __floats2bfloat162_rn(lo, hi);
    return *(uint32_t*)&h;
}
__device__ __forceinline__ void cpasync16(uint32_t s, const void* g) {
    asm volatile("cp.async.cg.shared.global [%0], [%1], 16;" :: "r"(s), "l"(g) : "memory");
}
__device__ __forceinline__ void cpasync_commit() {
    asm volatile("cp.async.commit_group;" ::: "memory");
}
template <int N>
__device__ __forceinline__ void cpasync_wait() {
    asm volatile("cp.async.wait_group %0;" :: "n"(N) : "memory");
}

// ==================== static scratch ====================
__device__ __nv_bfloat16 g_xthi[(size_t)NPIX * CIN];   // x transposed hi, [pix][512]
__device__ __nv_bfloat16 g_xtlo[(size_t)NPIX * CIN];   // x transposed lo
__device__ __nv_bfloat16 g_qthi[(size_t)NPIX * HALF];  // q transposed hi, [pix][256]
__device__ __nv_bfloat16 g_qtlo[(size_t)NPIX * HALF];
__device__ __nv_bfloat16 g_pthi[(size_t)NPIX * HALF];  // attn-out transposed hi, [pix][256]
__device__ __nv_bfloat16 g_ptlo[(size_t)NPIX * HALF];
__device__ __nv_bfloat16 g_whi[4][CIN * HALF];         // q,k,v,o weights hi
__device__ __nv_bfloat16 g_wlo[4][CIN * HALF];
__device__ __nv_bfloat16 g_ahi[(size_t)NUM * 1024 * 64];   // attn bf16 hi
__device__ __nv_bfloat16 g_alo[(size_t)NUM * 1024 * 64];   // attn bf16 lo
__device__ float g_kp[HALF * NUM];                     // pooled k [c][patch] fp32
__device__ float g_vp[NUM * HALF];                     // pooled v [patch][c] fp32
__device__ __nv_bfloat16 g_kpbh[NUM * HALF];           // kp bf16 hi, [patch][c]
__device__ __nv_bfloat16 g_kpbl[NUM * HALF];           // kp bf16 lo

// ==================== conversion kernels ====================
__global__ void conv_w4_kernel(const float* __restrict__ w0, const float* __restrict__ w1,
                               const float* __restrict__ w2, const float* __restrict__ w3,
                               __nv_bfloat16* __restrict__ hi, __nv_bfloat16* __restrict__ lo)
{
    const int wsel = blockIdx.y;
    const float* w = (wsel == 0) ? w0 : (wsel == 1) ? w1 : (wsel == 2) ? w2 : w3;
    int i = blockIdx.x * 256 + threadIdx.x;
    float v = w[i];
    __nv_bfloat16 h = __float2bfloat16(v);
    const size_t off = (size_t)wsel * (CIN * HALF) + i;
    hi[off] = h;
    lo[off] = __float2bfloat16(v - __bfloat162float(h));
}

// x [512][NPIX] fp32 -> XT [NPIX][512] bf16 hi/lo  (32x32 tile transpose, packed stores)
__global__ void conv_x_kernel(const float* __restrict__ x,
                              __nv_bfloat16* __restrict__ hi,
                              __nv_bfloat16* __restrict__ lo)
{
    __shared__ float t[32][33];
    const int p0 = blockIdx.x * 32;
    const int k0 = blockIdx.y * 32;
    const int tx = threadIdx.x, ty = threadIdx.y;   // (32, 8)
    #pragma unroll
    for (int i = 0; i < 4; i++) {
        int kl = ty + i * 8;
        t[kl][tx] = x[(size_t)(k0 + kl) * NPIX + p0 + tx];
    }
    __syncthreads();
    const int txh = tx & 15;            // channel pair index
    const int po = (tx >> 4) * 8 + ty;  // 0..15
    #pragma unroll
    for (int i = 0; i < 2; i++) {
        const int pl = po + i * 16;
        float v0 = t[2 * txh][pl];
        float v1 = t[2 * txh + 1][pl];
        __nv_bfloat16 h0 = __float2bfloat16(v0);
        __nv_bfloat16 h1 = __float2bfloat16(v1);
        const size_t off = (size_t)(p0 + pl) * CIN + k0 + 2 * txh;
        *(uint32_t*)(hi + off) = packbf2(v0, v1);
        *(uint32_t*)(lo + off) = packbf2(v0 - __bfloat162float(h0), v1 - __bfloat162float(h1));
    }
}

__global__ void zero_pool_kernel(float* kp, float* vp)
{
    int i = blockIdx.x * 256 + threadIdx.x;   // grid 64 -> 16384
    kp[i] = 0.f;
    vp[i] = 0.f;
}

// kp [c][patch] fp32 -> [patch][c] bf16 hi/lo
__global__ void kconv_kernel(const float* __restrict__ kp,
                             __nv_bfloat16* __restrict__ kph, __nv_bfloat16* __restrict__ kpl)
{
    int i = blockIdx.x * 256 + threadIdx.x;   // grid 64 -> 16384
    const int patch = i >> 8;
    const int c = i & 255;
    float v = kp[c * NUM + patch];
    __nv_bfloat16 h = __float2bfloat16(v);
    kph[patch * HALF + c] = h;
    kpl[patch * HALF + c] = __float2bfloat16(v - __bfloat162float(h));
}

// ==================== fused q/k/v HMMA projection (grid = (6, 512)) ====================
// Single barrier per K-chunk: wait -> bar -> issue(ch+1) -> compute(ch).
#define LDKB2 80                      // 32 bf16 = 64B + 16B pad
#define TILE2 (128 * LDKB2)           // 10240
#define BUFSET (4 * TILE2)            // 40960
#define PROJ_SMEM (2 * BUFSET)        // 81920

struct QKVParams {
    const __nv_bfloat16* whi[3];
    const __nv_bfloat16* wlo[3];
    const float* gg[3];
    const float* bb[3];
    const float* mm[3];
    const float* vv[3];
};

__global__ void __launch_bounds__(256, 2)
proj_qkv(QKVParams p,
         const __nv_bfloat16* __restrict__ Bhi, const __nv_bfloat16* __restrict__ Blo,
         __nv_bfloat16* __restrict__ qhi, __nv_bfloat16* __restrict__ qlo,
         float* __restrict__ kpo, float* __restrict__ vpo, float qscale)
{
    extern __shared__ char smc[];
    const uint32_t sb = smem_to_u32(smc);

    const int tid = threadIdx.x;
    const int wid = tid >> 5;
    const int lane = tid & 31;
    const int wm = wid & 1;
    const int wn = wid >> 1;
    const int wsel = blockIdx.x >> 1;     // 0=q 1=k 2=v (fast index -> L2 reuse of x)
    const int bmh = blockIdx.x & 1;       // out-ch tile
    const int pixbase = blockIdx.y * 128;

    const __nv_bfloat16* Ahi = p.whi[wsel];
    const __nv_bfloat16* Alo = p.wlo[wsel];

    float acc[4][4][4];
    #pragma unroll
    for (int mt = 0; mt < 4; mt++)
        #pragma unroll
        for (int nt = 0; nt < 4; nt++)
            #pragma unroll
            for (int e = 0; e < 4; e++) acc[mt][nt][e] = 0.f;

    const int am_ = lane & 15;
    const int ak_ = (lane >> 4) * 8;
    const int bn_ = (lane & 7) + ((lane >> 4) << 3);
    const int bk_ = ((lane >> 3) & 1) * 8;

    const int lr[2] = { tid >> 2, (tid + 256) >> 2 };
    const int lc = tid & 3;

    const int NCH = CIN / 32;   // 16

    {
        #pragma unroll
        for (int j = 0; j < 2; j++) {
            const int r = lr[j];
            const size_t arow = (size_t)(bmh * 128 + r) * CIN + lc * 8;
            const size_t brow = (size_t)(pixbase + r) * CIN + lc * 8;
            cpasync16(sb + 0 * TILE2 + r * LDKB2 + lc * 16, Ahi + arow);
            cpasync16(sb + 1 * TILE2 + r * LDKB2 + lc * 16, Alo + arow);
            cpasync16(sb + 2 * TILE2 + r * LDKB2 + lc * 16, Bhi + brow);
            cpasync16(sb + 3 * TILE2 + r * LDKB2 + lc * 16, Blo + brow);
        }
        cpasync_commit();
    }

    for (int ch = 0; ch < NCH; ch++) {
        cpasync_wait<0>();
        __syncthreads();          // chunk ch visible; compute(ch-1) done everywhere
        if (ch + 1 < NCH) {
            const uint32_t bufb = sb + ((ch + 1) & 1) * BUFSET;
            const int kc1 = (ch + 1) * 32;
            #pragma unroll
            for (int j = 0; j < 2; j++) {
                const int r = lr[j];
                const size_t arow = (size_t)(bmh * 128 + r) * CIN + kc1 + lc * 8;
                const size_t brow = (size_t)(pixbase + r) * CIN + kc1 + lc * 8;
                cpasync16(bufb + 0 * TILE2 + r * LDKB2 + lc * 16, Ahi + arow);
                cpasync16(bufb + 1 * TILE2 + r * LDKB2 + lc * 16, Alo + arow);
                cpasync16(bufb + 2 * TILE2 + r * LDKB2 + lc * 16, Bhi + brow);
                cpasync16(bufb + 3 * TILE2 + r * LDKB2 + lc * 16, Blo + brow);
            }
            cpasync_commit();
        }

        const uint32_t cb = sb + (ch & 1) * BUFSET;
        const uint32_t bAh = cb, bAl = cb + TILE2, bBh = cb + 2 * TILE2, bBl = cb + 3 * TILE2;
        #pragma unroll
        for (int ks = 0; ks < 2; ks++) {
            const int kc = ks * 16;
            uint32_t a[4][4], bh[4][2], bl[4][2];
            #pragma unroll
            for (int mt = 0; mt < 4; mt++)
                ldsm4(a[mt], bAh + (wm * 64 + mt * 16 + am_) * LDKB2 + (kc + ak_) * 2);
            #pragma unroll
            for (int pr = 0; pr < 2; pr++) {
                uint32_t r4[4];
                ldsm4(r4, bBh + (wn * 32 + pr * 16 + bn_) * LDKB2 + (kc + bk_) * 2);
                bh[2 * pr][0] = r4[0]; bh[2 * pr][1] = r4[1];
                bh[2 * pr + 1][0] = r4[2]; bh[2 * pr + 1][1] = r4[3];
            }
            #pragma unroll
            for (int mt = 0; mt < 4; mt++)
                #pragma unroll
                for (int nt = 0; nt < 4; nt++) mma16816(acc[mt][nt], a[mt], bh[nt]);
            #pragma unroll
            for (int pr = 0; pr < 2; pr++) {
                uint32_t r4[4];
                ldsm4(r4, bBl + (wn * 32 + pr * 16 + bn_) * LDKB2 + (kc + bk_) * 2);
                bl[2 * pr][0] = r4[0]; bl[2 * pr][1] = r4[1];
                bl[2 * pr + 1][0] = r4[2]; bl[2 * pr + 1][1] = r4[3];
            }
            #pragma unroll
            for (int mt = 0; mt < 4; mt++)
                #pragma unroll
                for (int nt = 0; nt < 4; nt++) mma16816(acc[mt][nt], a[mt], bl[nt]);
            #pragma unroll
            for (int mt = 0; mt < 4; mt++)
                ldsm4(a[mt], bAl + (wm * 64 + mt * 16 + am_) * LDKB2 + (kc + ak_) * 2);
            #pragma unroll
            for (int mt = 0; mt < 4; mt++)
                #pragma unroll
                for (int nt = 0; nt < 4; nt++) mma16816(acc[mt][nt], a[mt], bh[nt]);
        }
    }
    __syncthreads();   // all compute done before epilogue overlays buffers

    // ==================== epilogues ====================
    if (wsel >= 1) {
        const int x0 = (pixbase & 255) + wn * 32;
        const int y0 = pixbase >> 8;
        const int patch = ((y0 >> 5) << 3) + (x0 >> 5);
        const float inv = 1.f / 1024.f;
        const float* gg = p.gg[wsel];
        const float* bb = p.bb[wsel];
        const float* mm = p.mm[wsel];
        const float* vv = p.vv[wsel];
        float* outp = (wsel == 1) ? kpo : vpo;
        #pragma unroll
        for (int mt = 0; mt < 4; mt++) {
            #pragma unroll
            for (int hf = 0; hf < 2; hf++) {
                const int o = bmh * 128 + wm * 64 + mt * 16 + (lane >> 2) + hf * 8;
                const float s_r = gg[o] * rsqrtf(vv[o] + EPS);
                const float t_r = bb[o] - mm[o] * s_r;
                float s = 0.f;
                #pragma unroll
                for (int nt = 0; nt < 4; nt++) {
                    s += fmaxf(acc[mt][nt][2 * hf + 0] * s_r + t_r, 0.f);
                    s += fmaxf(acc[mt][nt][2 * hf + 1] * s_r + t_r, 0.f);
                }
                s += __shfl_xor_sync(0xffffffffu, s, 1);
                s += __shfl_xor_sync(0xffffffffu, s, 2);
                if ((lane & 3) == 0) {
                    if (wsel == 1) atomicAdd(outp + o * NUM + patch, s * inv);
                    else           atomicAdd(outp + patch * HALF + o, s * inv);
                }
            }
        }
    } else {
        // q: BN + ReLU + qscale, emit bf16 hi/lo [pix][256]
        float* stage = (float*)smc;                  // 128 x 131 fp32
        float* scb = (float*)(smc + 68608);
        float* bob = (float*)(smc + 69632);
        if (tid < 128) {
            const int o = bmh * 128 + tid;
            const float s_r = p.gg[0][o] * rsqrtf(p.vv[0][o] + EPS);
            scb[tid] = s_r;
            bob[tid] = p.bb[0][o] - p.mm[0][o] * s_r;
        }
        __syncthreads();
        #pragma unroll
        for (int mt = 0; mt < 4; mt++) {
            const int r_lo = wm * 64 + mt * 16 + (lane >> 2);
            #pragma unroll
            for (int nt = 0; nt < 4; nt++) {
                const int c = wn * 32 + nt * 8 + (lane & 3) * 2;
                stage[r_lo * 131 + c]     = fmaxf(acc[mt][nt][0] * scb[r_lo] + bob[r_lo], 0.f) * qscale;
                stage[r_lo * 131 + c + 1] = fmaxf(acc[mt][nt][1] * scb[r_lo] + bob[r_lo], 0.f) * qscale;
                stage[(r_lo + 8) * 131 + c]     = fmaxf(acc[mt][nt][2] * scb[r_lo + 8] + bob[r_lo + 8], 0.f) * qscale;
                stage[(r_lo + 8) * 131 + c + 1] = fmaxf(acc[mt][nt][3] * scb[r_lo + 8] + bob[r_lo + 8], 0.f) * qscale;
            }
        }
        __syncthreads();
        for (int i = tid; i < 128 * 64; i += 256) {
            const int pixl = i >> 6;
            const int cp = (i & 63) * 2;
            float v0 = stage[cp * 131 + pixl];
            float v1 = stage[(cp + 1) * 131 + pixl];
            __nv_bfloat16 h0 = __float2bfloat16(v0);
            __nv_bfloat16 h1 = __float2bfloat16(v1);
            const size_t off = (size_t)(pixbase + pixl) * HALF + bmh * 128 + cp;
            *(uint32_t*)(qhi + off) = packbf2(v0, v1);
            *(uint32_t*)(qlo + off) = packbf2(v0 - __bfloat162float(h0), v1 - __bfloat162float(h1));
        }
    }
}

// ==================== HMMA o-projection (grid = (4, 512)), single-barrier ====================
template <int KDIM>
__global__ void __launch_bounds__(256, 2)
proj_o(const __nv_bfloat16* __restrict__ Ahi, const __nv_bfloat16* __restrict__ Alo,
       const __nv_bfloat16* __restrict__ Bhi, const __nv_bfloat16* __restrict__ Blo,
       const float* __restrict__ gg, const float* __restrict__ bb,
       const float* __restrict__ mm, const float* __restrict__ vv,
       float* __restrict__ outp, const float* __restrict__ resid)
{
    extern __shared__ char smc[];
    const uint32_t sb = smem_to_u32(smc);

    const int tid = threadIdx.x;
    const int wid = tid >> 5;
    const int lane = tid & 31;
    const int wm = wid & 1;
    const int wn = wid >> 1;
    const int bm = blockIdx.x;            // fast -> L2 reuse of B
    const int pixbase = blockIdx.y * 128;

    float acc[4][4][4];
    #pragma unroll
    for (int mt = 0; mt < 4; mt++)
        #pragma unroll
        for (int nt = 0; nt < 4; nt++)
            #pragma unroll
            for (int e = 0; e < 4; e++) acc[mt][nt][e] = 0.f;

    const int am_ = lane & 15;
    const int ak_ = (lane >> 4) * 8;
    const int bn_ = (lane & 7) + ((lane >> 4) << 3);
    const int bk_ = ((lane >> 3) & 1) * 8;

    const int lr[2] = { tid >> 2, (tid + 256) >> 2 };
    const int lc = tid & 3;

    const int NCH = KDIM / 32;

    {
        #pragma unroll
        for (int j = 0; j < 2; j++) {
            const int r = lr[j];
            const size_t arow = (size_t)(bm * 128 + r) * KDIM + lc * 8;
            const size_t brow = (size_t)(pixbase + r) * KDIM + lc * 8;
            cpasync16(sb + 0 * TILE2 + r * LDKB2 + lc * 16, Ahi + arow);
            cpasync16(sb + 1 * TILE2 + r * LDKB2 + lc * 16, Alo + arow);
            cpasync16(sb + 2 * TILE2 + r * LDKB2 + lc * 16, Bhi + brow);
            cpasync16(sb + 3 * TILE2 + r * LDKB2 + lc * 16, Blo + brow);
        }
        cpasync_commit();
    }

    for (int ch = 0; ch < NCH; ch++) {
        cpasync_wait<0>();
        __syncthreads();
        if (ch + 1 < NCH) {
            const uint32_t bufb = sb + ((ch + 1) & 1) * BUFSET;
            const int kc1 = (ch + 1) * 32;
            #pragma unroll
            for (int j = 0; j < 2; j++) {
                const int r = lr[j];
                const size_t arow = (size_t)(bm * 128 + r) * KDIM + kc1 + lc * 8;
                const size_t brow = (size_t)(pixbase + r) * KDIM + kc1 + lc * 8;
                cpasync16(bufb + 0 * TILE2 + r * LDKB2 + lc * 16, Ahi + arow);
                cpasync16(bufb + 1 * TILE2 + r * LDKB2 + lc * 16, Alo + arow);
                cpasync16(bufb + 2 * TILE2 + r * LDKB2 + lc * 16, Bhi + brow);
                cpasync16(bufb + 3 * TILE2 + r * LDKB2 + lc * 16, Blo + brow);
            }
            cpasync_commit();
        }

        const uint32_t cb = sb + (ch & 1) * BUFSET;
        const uint32_t bAh = cb, bAl = cb + TILE2, bBh = cb + 2 * TILE2, bBl = cb + 3 * TILE2;
        #pragma unroll
        for (int ks = 0; ks < 2; ks++) {
            const int kc = ks * 16;
            uint32_t a[4][4], bh[4][2], bl[4][2];
            #pragma unroll
            for (int mt = 0; mt < 4; mt++)
                ldsm4(a[mt], bAh + (wm * 64 + mt * 16 + am_) * LDKB2 + (kc + ak_) * 2);
            #pragma unroll
            for (int pr = 0; pr < 2; pr++) {
                uint32_t r4[4];
                ldsm4(r4, bBh + (wn * 32 + pr * 16 + bn_) * LDKB2 + (kc + bk_) * 2);
                bh[2 * pr][0] = r4[0]; bh[2 * pr][1] = r4[1];
                bh[2 * pr + 1][0] = r4[2]; bh[2 * pr + 1][1] = r4[3];
            }
            #pragma unroll
            for (int mt = 0; mt < 4; mt++)
                #pragma unroll
                for (int nt = 0; nt < 4; nt++) mma16816(acc[mt][nt], a[mt], bh[nt]);
            #pragma unroll
            for (int pr = 0; pr < 2; pr++) {
                uint32_t r4[4];
                ldsm4(r4, bBl + (wn * 32 + pr * 16 + bn_) * LDKB2 + (kc + bk_) * 2);
                bl[2 * pr][0] = r4[0]; bl[2 * pr][1] = r4[1];
                bl[2 * pr + 1][0] = r4[2]; bl[2 * pr + 1][1] = r4[3];
            }
            #pragma unroll
            for (int mt = 0; mt < 4; mt++)
                #pragma unroll
                for (int nt = 0; nt < 4; nt++) mma16816(acc[mt][nt], a[mt], bl[nt]);
            #pragma unroll
            for (int mt = 0; mt < 4; mt++)
                ldsm4(a[mt], bAl + (wm * 64 + mt * 16 + am_) * LDKB2 + (kc + ak_) * 2);
            #pragma unroll
            for (int mt = 0; mt < 4; mt++)
                #pragma unroll
                for (int nt = 0; nt < 4; nt++) mma16816(acc[mt][nt], a[mt], bh[nt]);
        }
    }
    __syncthreads();

    float* stage = (float*)smc;
    float* scb = (float*)(smc + 68608);
    float* bob = (float*)(smc + 69632);
    if (tid < 128) {
        const int o = bm * 128 + tid;
        const float s_r = gg[o] * rsqrtf(vv[o] + EPS);
        scb[tid] = s_r;
        bob[tid] = bb[o] - mm[o] * s_r;
    }
    __syncthreads();
    #pragma unroll
    for (int mt = 0; mt < 4; mt++) {
        const int r_lo = wm * 64 + mt * 16 + (lane >> 2);
        #pragma unroll
        for (int nt = 0; nt < 4; nt++) {
            const int c = wn * 32 + nt * 8 + (lane & 3) * 2;
            stage[r_lo * 130 + c]     = fmaxf(acc[mt][nt][0] * scb[r_lo] + bob[r_lo], 0.f);
            stage[r_lo * 130 + c + 1] = fmaxf(acc[mt][nt][1] * scb[r_lo] + bob[r_lo], 0.f);
            stage[(r_lo + 8) * 130 + c]     = fmaxf(acc[mt][nt][2] * scb[r_lo + 8] + bob[r_lo + 8], 0.f);
            stage[(r_lo + 8) * 130 + c + 1] = fmaxf(acc[mt][nt][3] * scb[r_lo + 8] + bob[r_lo + 8], 0.f);
        }
    }
    __syncthreads();
    for (int i = tid; i < 128 * 128; i += 256) {
        const int r = i >> 7;
        const int c = i & 127;
        const size_t go = (size_t)(bm * 128 + r) * NPIX + pixbase + c;
        outp[go] = stage[r * 130 + c] + resid[go];
    }
}

// ==================== attn via mma.sync, single-barrier ====================
#define AT_KPH 0
#define AT_KPSTR 528
#define AT_KPL (64 * AT_KPSTR)          // 33792
#define AT_QB  (2 * 64 * AT_KPSTR)      // 67584
#define AT_QBSZ (2 * 128 * LDKB2)       // 20480
#define AT_SMEM (AT_QB + 2 * AT_QBSZ)   // 108544
__global__ void __launch_bounds__(256, 2)
attn_mma(const __nv_bfloat16* __restrict__ qhi, const __nv_bfloat16* __restrict__ qlo,
         const __nv_bfloat16* __restrict__ kph, const __nv_bfloat16* __restrict__ kpl,
         __nv_bfloat16* __restrict__ ahi, __nv_bfloat16* __restrict__ alo)
{
    extern __shared__ char smc[];
    const uint32_t sb = smem_to_u32(smc);

    const int rowblk = blockIdx.x;
    const int b = blockIdx.y;
    const int tid = threadIdx.x;
    const int wid = tid >> 5;
    const int lane = tid & 31;
    const int ph = b >> 3, pw = b & 7;
    const int pixbase = ph * 32 * WW + pw * 32;

    #pragma unroll
    for (int j = 0; j < 8; j++) {
        const int idx = tid + j * 256;       // 0..2047
        const int r = idx >> 5;
        const int c16 = idx & 31;
        *(uint4*)(smc + AT_KPH + r * AT_KPSTR + c16 * 16) = *(const uint4*)(kph + r * HALF + c16 * 8);
        *(uint4*)(smc + AT_KPL + r * AT_KPSTR + c16 * 16) = *(const uint4*)(kpl + r * HALF + c16 * 8);
    }

    const int qr[2] = { tid >> 2, (tid + 256) >> 2 };
    const int qc = tid & 3;
    int qpix[2];
    #pragma unroll
    for (int j = 0; j < 2; j++) {
        const int n = rowblk * 128 + qr[j];
        qpix[j] = pixbase + (n >> 5) * WW + (n & 31);
    }

    {
        const uint32_t qb = sb + AT_QB;
        #pragma unroll
        for (int j = 0; j < 2; j++) {
            const size_t g = (size_t)qpix[j] * HALF + qc * 8;
            cpasync16(qb + qr[j] * LDKB2 + qc * 16, qhi + g);
            cpasync16(qb + 128 * LDKB2 + qr[j] * LDKB2 + qc * 16, qlo + g);
        }
        cpasync_commit();
    }

    const int am_ = lane & 15;
    const int ak_ = (lane >> 4) * 8;
    const int bn_ = (lane & 7) + ((lane >> 4) << 3);
    const int bk_ = ((lane >> 3) & 1) * 8;
    const int grp = lane >> 2;
    const int qd = lane & 3;

    float S[8][4];
    #pragma unroll
    for (int nt = 0; nt < 8; nt++)
        #pragma unroll
        for (int e = 0; e < 4; e++) S[nt][e] = 0.f;

    const int NCH = HALF / 32;   // 8
    for (int ch = 0; ch < NCH; ch++) {
        cpasync_wait<0>();
        __syncthreads();          // chunk ch + kp visible; compute(ch-1) done
        if (ch + 1 < NCH) {
            const uint32_t qb = sb + AT_QB + ((ch + 1) & 1) * AT_QBSZ;
            const int kc1 = (ch + 1) * 32;
            #pragma unroll
            for (int j = 0; j < 2; j++) {
                const size_t g = (size_t)qpix[j] * HALF + kc1 + qc * 8;
                cpasync16(qb + qr[j] * LDKB2 + qc * 16, qhi + g);
                cpasync16(qb + 128 * LDKB2 + qr[j] * LDKB2 + qc * 16, qlo + g);
            }
            cpasync_commit();
        }

        const uint32_t qb = sb + AT_QB + (ch & 1) * AT_QBSZ;
        const uint32_t qHI = qb, qLO = qb + 128 * LDKB2;
        #pragma unroll
        for (int ks = 0; ks < 2; ks++) {
            const int kc = ks * 16;
            const int kb = (ch * 32 + kc) * 2;
            uint32_t a[4], bh[8][2], bl[8][2];
            ldsm4(a, qHI + (wid * 16 + am_) * LDKB2 + (kc + ak_) * 2);
            #pragma unroll
            for (int pr = 0; pr < 4; pr++) {
                uint32_t r4[4];
                ldsm4(r4, sb + AT_KPH + (pr * 16 + bn_) * AT_KPSTR + kb + bk_ * 2);
                bh[2 * pr][0] = r4[0]; bh[2 * pr][1] = r4[1];
                bh[2 * pr + 1][0] = r4[2]; bh[2 * pr + 1][1] = r4[3];
            }
            #pragma unroll
            for (int nt = 0; nt < 8; nt++) mma16816(S[nt], a, bh[nt]);
            #pragma unroll
            for (int pr = 0; pr < 4; pr++) {
                uint32_t r4[4];
                ldsm4(r4, sb + AT_KPL + (pr * 16 + bn_) * AT_KPSTR + kb + bk_ * 2);
                bl[2 * pr][0] = r4[0]; bl[2 * pr][1] = r4[1];
                bl[2 * pr + 1][0] = r4[2]; bl[2 * pr + 1][1] = r4[3];
            }
            #pragma unroll
            for (int nt = 0; nt < 8; nt++) mma16816(S[nt], a, bl[nt]);
            ldsm4(a, qLO + (wid * 16 + am_) * LDKB2 + (kc + ak_) * 2);
            #pragma unroll
            for (int nt = 0; nt < 8; nt++) mma16816(S[nt], a, bh[nt]);
        }
    }

    const int r1 = wid * 16 + grp;
    #pragma unroll
    for (int nt = 0; nt < 8; nt++) {
        const int col = nt * 8 + qd * 2;
        {
            const int n = rowblk * 128 + r1;
            const size_t off = ((size_t)b * 1024 + n) * 64 + col;
            float v0 = S[nt][0], v1 = S[nt][1];
            __nv_bfloat16 h0 = __float2bfloat16(v0);
            __nv_bfloat16 h1 = __float2bfloat16(v1);
            *(uint32_t*)(ahi + off) = packbf2(v0, v1);
            *(uint32_t*)(alo + off) = packbf2(v0 - __bfloat162float(h0), v1 - __bfloat162float(h1));
        }
        {
            const int n = rowblk * 128 + r1 + 8;
            const size_t off = ((size_t)b * 1024 + n) * 64 + col;
            float v0 = S[nt][2], v1 = S[nt][3];
            __nv_bfloat16 h0 = __float2bfloat16(v0);
            __nv_bfloat16 h1 = __float2bfloat16(v1);
            *(uint32_t*)(ahi + off) = packbf2(v0, v1);
            *(uint32_t*)(alo + off) = packbf2(v0 - __bfloat162float(h0), v1 - __bfloat162float(h1));
        }
    }
}

// ==================== flash v3: mma.sync nested-softmax attention ====================
#define FLDB 144                 // bf16 tile stride bytes
#define F_QHI 0
#define F_QLO 9216
#define F_KB   18432             // K buffers: base + buf*18432; KHI at +0, KLO at +9216
#define F_REDM 55296             // float[64][4]
#define F_REDS 56320             // float[64][4]
#define F_MS   57344             // float[64]
#define F_LS   57600
#define F_SCS  57856
#define F_MNS  58112
#define F_REDF 58368             // float[64][16]
#define F_TOTAL 62464
__global__ void __launch_bounds__(256, 2)
flash3_kernel(const __nv_bfloat16* __restrict__ ahi, const __nv_bfloat16* __restrict__ alo,
              const float* __restrict__ vp,
              __nv_bfloat16* __restrict__ pthi, __nv_bfloat16* __restrict__ ptlo)
{
    extern __shared__ char smc[];
    const uint32_t sb = smem_to_u32(smc);
    float* REDM = (float*)(smc + F_REDM);
    float* REDS = (float*)(smc + F_REDS);
    float* m_s  = (float*)(smc + F_MS);
    float* l_s  = (float*)(smc + F_LS);
    float* sc_s = (float*)(smc + F_SCS);
    float* mn_s = (float*)(smc + F_MNS);
    float* REDF = (float*)(smc + F_REDF);

    const int rblk = blockIdx.x;    // 0..15
    const int b = blockIdx.y;       // patch
    const int tid = threadIdx.x;
    const int lane = tid & 31;
    const int wid = tid >> 5;
    const int wm = wid >> 2;        // 0..1
    const int wn = wid & 3;         // 0..3
    const int r0 = rblk * 64;
    const size_t abase = (size_t)b * 1024 * 64;

    if (tid < 64) { m_s[tid] = -1e30f; l_s[tid] = 0.f; }

    const int kr[2] = { tid >> 3, (tid + 256) >> 3 };
    const int kc_ = tid & 7;

    {
        const uint32_t kb = sb + F_KB;
        #pragma unroll
        for (int j = 0; j < 2; j++) {
            const int r = kr[j];
            const size_t g = abase + (size_t)r * 64 + kc_ * 8;
            cpasync16(kb + r * FLDB + kc_ * 16, ahi + g);
            cpasync16(kb + 9216 + r * FLDB + kc_ * 16, alo + g);
        }
        cpasync_commit();
    }

    {
        #pragma unroll
        for (int i = 0; i < 2; i++) {
            const int idx = tid + i * 256;
            const int r = idx >> 3;
            const int c = idx & 7;
            const size_t g = abase + (size_t)(r0 + r) * 64 + c * 8;
            *(uint4*)(smc + F_QHI + r * FLDB + c * 16) = *(const uint4*)(ahi + g);
            *(uint4*)(smc + F_QLO + r * FLDB + c * 16) = *(const uint4*)(alo + g);
        }
    }

    const int am_ = lane & 15;
    const int ak_ = (lane >> 4) * 8;
    const int bn_ = (lane & 7) + ((lane >> 4) << 3);
    const int bk_ = ((lane >> 3) & 1) * 8;
    const int vk_ = lane & 15;
    const int vn_ = (lane >> 4) << 3;
    const int grp = lane >> 2;
    const int qd  = lane & 3;

    float O[2][8][4];
    #pragma unroll
    for (int mt = 0; mt < 2; mt++)
        #pragma unroll
        for (int n8 = 0; n8 < 8; n8++)
            #pragma unroll
            for (int e = 0; e < 4; e++) O[mt][n8][e] = 0.f;

    for (int t = 0; t < 16; t++) {
        cpasync_wait<0>();
        __syncthreads();          // tile t + Q visible; GEMM2(t-1) + REDS(t-1) done
        if (t > 0 && tid < 64) {
            l_s[tid] = l_s[tid] * sc_s[tid]
                     + REDS[tid * 4 + 0] + REDS[tid * 4 + 1]
                     + REDS[tid * 4 + 2] + REDS[tid * 4 + 3];
        }
        if (t + 1 < 16) {
            const uint32_t kb = sb + F_KB + ((t + 1) & 1) * 18432;
            #pragma unroll
            for (int j = 0; j < 2; j++) {
                const int r = kr[j];
                const size_t g = abase + (size_t)((t + 1) * 64 + r) * 64 + kc_ * 8;
                cpasync16(kb + r * FLDB + kc_ * 16, ahi + g);
                cpasync16(kb + 9216 + r * FLDB + kc_ * 16, alo + g);
            }
            cpasync_commit();
        }

        const uint32_t kb = sb + F_KB + (t & 1) * 18432;
        const uint32_t kHI = kb, kLO = kb + 9216;

        float S[2][2][4];
        #pragma unroll
        for (int mt = 0; mt < 2; mt++)
            #pragma unroll
            for (int nt = 0; nt < 2; nt++)
                #pragma unroll
                for (int e = 0; e < 4; e++) S[mt][nt][e] = 0.f;
        #pragma unroll
        for (int ks = 0; ks < 4; ks++) {
            const int kc = ks * 16;
            uint32_t a[2][4], bh[2][2], bl[2][2];
            #pragma unroll
            for (int mt = 0; mt < 2; mt++)
                ldsm4(a[mt], sb + F_QHI + (wm * 32 + mt * 16 + am_) * FLDB + (kc + ak_) * 2);
            {
                uint32_t r4[4];
                ldsm4(r4, kHI + (wn * 16 + bn_) * FLDB + (kc + bk_) * 2);
                bh[0][0] = r4[0]; bh[0][1] = r4[1]; bh[1][0] = r4[2]; bh[1][1] = r4[3];
            }
            #pragma unroll
            for (int mt = 0; mt < 2; mt++)
                #pragma unroll
                for (int nt = 0; nt < 2; nt++) mma16816(S[mt][nt], a[mt], bh[nt]);
            {
                uint32_t r4[4];
                ldsm4(r4, kLO + (wn * 16 + bn_) * FLDB + (kc + bk_) * 2);
                bl[0][0] = r4[0]; bl[0][1] = r4[1]; bl[1][0] = r4[2]; bl[1][1] = r4[3];
            }
            #pragma unroll
            for (int mt = 0; mt < 2; mt++)
                #pragma unroll
                for (int nt = 0; nt < 2; nt++) mma16816(S[mt][nt], a[mt], bl[nt]);
            #pragma unroll
            for (int mt = 0; mt < 2; mt++)
                ldsm4(a[mt], sb + F_QLO + (wm * 32 + mt * 16 + am_) * FLDB + (kc + ak_) * 2);
            #pragma unroll
            for (int mt = 0; mt < 2; mt++)
                #pragma unroll
                for (int nt = 0; nt < 2; nt++) mma16816(S[mt][nt], a[mt], bh[nt]);
        }

        #pragma unroll
        for (int mt = 0; mt < 2; mt++) {
            float la = fmaxf(fmaxf(S[mt][0][0], S[mt][0][1]), fmaxf(S[mt][1][0], S[mt][1][1]));
            float lb = fmaxf(fmaxf(S[mt][0][2], S[mt][0][3]), fmaxf(S[mt][1][2], S[mt][1][3]));
            la = fmaxf(la, __shfl_xor_sync(0xffffffffu, la, 1));
            la = fmaxf(la, __shfl_xor_sync(0xffffffffu, la, 2));
            lb = fmaxf(lb, __shfl_xor_sync(0xffffffffu, lb, 1));
            lb = fmaxf(lb, __shfl_xor_sync(0xffffffffu, lb, 2));
            if (qd == 0) {
                const int r1 = wm * 32 + mt * 16 + grp;
                REDM[r1 * 4 + wn] = la;
                REDM[(r1 + 8) * 4 + wn] = lb;
            }
        }
        __syncthreads();
        if (tid < 64) {
            float mt_ = fmaxf(fmaxf(REDM[tid * 4], REDM[tid * 4 + 1]),
                              fmaxf(REDM[tid * 4 + 2], REDM[tid * 4 + 3]));
            const float mo = m_s[tid];
            const float mn = fmaxf(mo, mt_);
            sc_s[tid] = __expf(mo - mn);
            mn_s[tid] = mn;
            m_s[tid] = mn;
        }
        __syncthreads();

        uint32_t aPh[2][4], aPl[2][4];
        #pragma unroll
        for (int mt = 0; mt < 2; mt++) {
            const int r1 = wm * 32 + mt * 16 + grp;
            const float mna = mn_s[r1];
            const float mnb = mn_s[r1 + 8];
            float P[2][4];
            #pragma unroll
            for (int nt = 0; nt < 2; nt++) {
                P[nt][0] = __expf(S[mt][nt][0] - mna);
                P[nt][1] = __expf(S[mt][nt][1] - mna);
                P[nt][2] = __expf(S[mt][nt][2] - mnb);
                P[nt][3] = __expf(S[mt][nt][3] - mnb);
            }
            float ra = P[0][0] + P[0][1] + P[1][0] + P[1][1];
            float rb = P[0][2] + P[0][3] + P[1][2] + P[1][3];
            ra += __shfl_xor_sync(0xffffffffu, ra, 1);
            ra += __shfl_xor_sync(0xffffffffu, ra, 2);
            rb += __shfl_xor_sync(0xffffffffu, rb, 1);
            rb += __shfl_xor_sync(0xffffffffu, rb, 2);
            if (qd == 0) {
                REDS[r1 * 4 + wn] = ra;
                REDS[(r1 + 8) * 4 + wn] = rb;
            }
            aPh[mt][0] = packbf2(P[0][0], P[0][1]);
            aPh[mt][1] = packbf2(P[0][2], P[0][3]);
            aPh[mt][2] = packbf2(P[1][0], P[1][1]);
            aPh[mt][3] = packbf2(P[1][2], P[1][3]);
            float l00 = P[0][0] - __bfloat162float(__float2bfloat16(P[0][0]));
            float l01 = P[0][1] - __bfloat162float(__float2bfloat16(P[0][1]));
            float l02 = P[0][2] - __bfloat162float(__float2bfloat16(P[0][2]));
            float l03 = P[0][3] - __bfloat162float(__float2bfloat16(P[0][3]));
            float l10 = P[1][0] - __bfloat162float(__float2bfloat16(P[1][0]));
            float l11 = P[1][1] - __bfloat162float(__float2bfloat16(P[1][1]));
            float l12 = P[1][2] - __bfloat162float(__float2bfloat16(P[1][2]));
            float l13 = P[1][3] - __bfloat162float(__float2bfloat16(P[1][3]));
            aPl[mt][0] = packbf2(l00, l01);
            aPl[mt][1] = packbf2(l02, l03);
            aPl[mt][2] = packbf2(l10, l11);
            aPl[mt][3] = packbf2(l12, l13);
            const float sa = sc_s[r1];
            const float sbx = sc_s[r1 + 8];
            #pragma unroll
            for (int n8 = 0; n8 < 8; n8++) {
                O[mt][n8][0] *= sa; O[mt][n8][1] *= sa;
                O[mt][n8][2] *= sbx; O[mt][n8][3] *= sbx;
            }
        }

        #pragma unroll
        for (int g = 0; g < 4; g++) {
            const int n0 = g * 16;
            uint32_t vh[4], vl[4];
            ldsm4t(vh, kHI + (wn * 16 + vk_) * FLDB + (n0 + vn_) * 2);
            ldsm4t(vl, kLO + (wn * 16 + vk_) * FLDB + (n0 + vn_) * 2);
            uint32_t b0h[2] = { vh[0], vh[1] }, b1h[2] = { vh[2], vh[3] };
            uint32_t b0l[2] = { vl[0], vl[1] }, b1l[2] = { vl[2], vl[3] };
            #pragma unroll
            for (int mt = 0; mt < 2; mt++) {
                mma16816(O[mt][2 * g + 0], aPh[mt], b0h);
                mma16816(O[mt][2 * g + 1], aPh[mt], b1h);
                mma16816(O[mt][2 * g + 0], aPh[mt], b0l);
                mma16816(O[mt][2 * g + 1], aPh[mt], b1l);
                mma16816(O[mt][2 * g + 0], aPl[mt], b0h);
                mma16816(O[mt][2 * g + 1], aPl[mt], b1h);
            }
        }
    }
    __syncthreads();
    if (tid < 64) {
        l_s[tid] = l_s[tid] * sc_s[tid]
                 + REDS[tid * 4 + 0] + REDS[tid * 4 + 1]
                 + REDS[tid * 4 + 2] + REDS[tid * 4 + 3];
    }

    float* Os = (float*)(smc + 0);          // [64][66]
    for (int i = tid; i < 64 * 66; i += 256) Os[i] = 0.f;
    __syncthreads();
    #pragma unroll 1
    for (int p = 0; p < 4; p++) {
        if (wn == p) {
            #pragma unroll
            for (int mt = 0; mt < 2; mt++) {
                const int r1 = wm * 32 + mt * 16 + grp;
                #pragma unroll
                for (int n8 = 0; n8 < 8; n8++) {
                    const int c = n8 * 8 + qd * 2;
                    Os[r1 * 66 + c]       += O[mt][n8][0];
                    Os[r1 * 66 + c + 1]   += O[mt][n8][1];
                    Os[(r1 + 8) * 66 + c]     += O[mt][n8][2];
                    Os[(r1 + 8) * 66 + c + 1] += O[mt][n8][3];
                }
            }
        }
        __syncthreads();
    }

    const int txx = tid & 15;
    const int tyy = tid >> 4;
    float fv[4][4];
    #pragma unroll
    for (int i = 0; i < 4; i++) {
        const int rr = tyy * 4 + i;
        const float linv = 1.f / l_s[rr];
        const size_t goff = abase + (size_t)(r0 + rr) * 64 + txx * 4;
        uint2 uh = *(const uint2*)(ahi + goff);
        uint2 ul = *(const uint2*)(alo + goff);
        __nv_bfloat162 h0 = *(__nv_bfloat162*)&uh.x;
        __nv_bfloat162 h1 = *(__nv_bfloat162*)&uh.y;
        __nv_bfloat162 l0 = *(__nv_bfloat162*)&ul.x;
        __nv_bfloat162 l1 = *(__nv_bfloat162*)&ul.y;
        fv[i][0] = __bfloat162float(h0.x) + __bfloat162float(l0.x) + Os[rr * 66 + txx * 4 + 0] * linv;
        fv[i][1] = __bfloat162float(h0.y) + __bfloat162float(l0.y) + Os[rr * 66 + txx * 4 + 1] * linv;
        fv[i][2] = __bfloat162float(h1.x) + __bfloat162float(l1.x) + Os[rr * 66 + txx * 4 + 2] * linv;
        fv[i][3] = __bfloat162float(h1.y) + __bfloat162float(l1.y) + Os[rr * 66 + txx * 4 + 3] * linv;
    }
    #pragma unroll
    for (int i = 0; i < 4; i++) {
        float lm = fmaxf(fmaxf(fv[i][0], fv[i][1]), fmaxf(fv[i][2], fv[i][3]));
        REDF[(tyy * 4 + i) * 16 + txx] = lm;
    }
    __syncthreads();
    if (tid < 64) {
        float mt_ = REDF[tid * 16];
        #pragma unroll
        for (int j = 1; j < 16; j++) mt_ = fmaxf(mt_, REDF[tid * 16 + j]);
        mn_s[tid] = mt_;
    }
    __syncthreads();
    #pragma unroll
    for (int i = 0; i < 4; i++) {
        const int rr = tyy * 4 + i;
        const float mn = mn_s[rr];
        float rs = 0.f;
        #pragma unroll
        for (int j = 0; j < 4; j++) { fv[i][j] = __expf(fv[i][j] - mn); rs += fv[i][j]; }
        REDF[rr * 16 + txx] = rs;
    }
    __syncthreads();
    if (tid < 64) {
        float su = REDF[tid * 16];
        #pragma unroll
        for (int j = 1; j < 16; j++) su += REDF[tid * 16 + j];
        l_s[tid] = 1.f / su;
    }
    __syncthreads();
    float* Ps = (float*)(smc + F_KB);       // [64][68] overlay on K buf0
    #pragma unroll
    for (int i = 0; i < 4; i++) {
        const int rr = tyy * 4 + i;
        const float inv = l_s[rr];
        *(float4*)&Ps[rr * 68 + txx * 4] =
            make_float4(fv[i][0] * inv, fv[i][1] * inv, fv[i][2] * inv, fv[i][3] * inv);
    }
    __syncthreads();

    float acc[4][16];
    #pragma unroll
    for (int i = 0; i < 4; i++)
        #pragma unroll
        for (int j = 0; j < 16; j++) acc[i][j] = 0.f;
    #pragma unroll 2
    for (int m = 0; m < 64; m++) {
        float pr[4];
        #pragma unroll
        for (int i = 0; i < 4; i++) pr[i] = Ps[(tyy * 4 + i) * 68 + m];
        const float4* vr = (const float4*)(vp + m * 256 + txx * 16);
        float4 v0 = vr[0], v1 = vr[1], v2 = vr[2], v3 = vr[3];
        const float vw[16] = {v0.x, v0.y, v0.z, v0.w, v1.x, v1.y, v1.z, v1.w,
                              v2.x, v2.y, v2.z, v2.w, v3.x, v3.y, v3.z, v3.w};
        #pragma unroll
        for (int i = 0; i < 4; i++)
            #pragma unroll
            for (int j = 0; j < 16; j++) acc[i][j] += pr[i] * vw[j];
    }

    const int ph = b >> 3, pw = b & 7;
    const int pixbase = ph * 32 * WW + pw * 32;
    float* stg = (float*)(smc + 0);
    #pragma unroll 1
    for (int g = 0; g < 4; g++) {
        __syncthreads();
        if ((txx >> 2) == g) {
            const int txl = txx & 3;
            #pragma unroll
            for (int i = 0; i < 4; i++)
                #pragma unroll
                for (int j = 0; j < 16; j++)
                    stg[(tyy * 4 + i) * 65 + txl * 16 + j] = acc[i][j];
        }
        __syncthreads();
        const int rl = tid >> 2;
        const int cc0 = (tid & 3) * 16;
        const int n = r0 + rl;
        const int pix = pixbase + (n >> 5) * WW + (n & 31);
        #pragma unroll
        for (int k2 = 0; k2 < 16; k2++) {
            float v = stg[rl * 65 + cc0 + k2];
            __nv_bfloat16 h = __float2bfloat16(v);
            const size_t off = (size_t)pix * HALF + g * 64 + cc0 + k2;
            pthi[off] = h;
            ptlo[off] = __float2bfloat16(v - __bfloat162float(h));
        }
    }
}

// ==================== launch ====================
extern "C" void kernel_launch(void* const* d_in, const int* in_sizes, int n_in,
                              void* d_out, int out_size)
{
    const float* x   = (const float*)d_in[0];
    const float* q_w = (const float*)d_in[1];
    const float* q_g = (const float*)d_in[2];
    const float* q_b = (const float*)d_in[3];
    const float* q_m = (const float*)d_in[4];
    const float* q_v = (const float*)d_in[5];
    const float* k_w = (const float*)d_in[6];
    const float* k_g = (const float*)d_in[7];
    const float* k_b = (const float*)d_in[8];
    const float* k_m = (const float*)d_in[9];
    const float* k_v = (const float*)d_in[10];
    const float* v_w = (const float*)d_in[11];
    const float* v_g = (const float*)d_in[12];
    const float* v_b = (const float*)d_in[13];
    const float* v_m = (const float*)d_in[14];
    const float* v_v = (const float*)d_in[15];
    const float* o_w = (const float*)d_in[16];
    const float* o_g = (const float*)d_in[17];
    const float* o_b = (const float*)d_in[18];
    const float* o_m = (const float*)d_in[19];
    const float* o_v = (const float*)d_in[20];
    float* out = (float*)d_out;

    __nv_bfloat16 *xthi, *xtlo, *qthi, *qtlo, *pthi, *ptlo, *ahi, *alo, *kpbh, *kpbl;
    __nv_bfloat16 (*whi)[CIN * HALF], (*wlo)[CIN * HALF];
    float *gkp, *gvp;
    cudaGetSymbolAddress((void**)&xthi, g_xthi);
    cudaGetSymbolAddress((void**)&xtlo, g_xtlo);
    cudaGetSymbolAddress((void**)&qthi, g_qthi);
    cudaGetSymbolAddress((void**)&qtlo, g_qtlo);
    cudaGetSymbolAddress((void**)&pthi, g_pthi);
    cudaGetSymbolAddress((void**)&ptlo, g_ptlo);
    cudaGetSymbolAddress((void**)&ahi, g_ahi);
    cudaGetSymbolAddress((void**)&alo, g_alo);
    cudaGetSymbolAddress((void**)&kpbh, g_kpbh);
    cudaGetSymbolAddress((void**)&kpbl, g_kpbl);
    cudaGetSymbolAddress((void**)&whi, g_whi);
    cudaGetSymbolAddress((void**)&wlo, g_wlo);
    cudaGetSymbolAddress((void**)&gkp, g_kp);
    cudaGetSymbolAddress((void**)&gvp, g_vp);

    const float qscale = 0.044194173824159216f;   // 512^-0.5

    // conversions
    conv_w4_kernel<<<dim3(512, 4), 256>>>(q_w, k_w, v_w, o_w, (__nv_bfloat16*)whi, (__nv_bfloat16*)wlo);
    conv_x_kernel<<<dim3(NPIX / 32, CIN / 32), dim3(32, 8)>>>(x, xthi, xtlo);
    zero_pool_kernel<<<64, 256>>>(gkp, gvp);

    // fused q/k/v projections (proj-slice fast -> L2 reuse of x tiles)
    QKVParams p;
    p.whi[0] = whi[0]; p.whi[1] = whi[1]; p.whi[2] = whi[2];
    p.wlo[0] = wlo[0]; p.wlo[1] = wlo[1]; p.wlo[2] = wlo[2];
    p.gg[0] = q_g; p.gg[1] = k_g; p.gg[2] = v_g;
    p.bb[0] = q_b; p.bb[1] = k_b; p.bb[2] = v_b;
    p.mm[0] = q_m; p.mm[1] = k_m; p.mm[2] = v_m;
    p.vv[0] = q_v; p.vv[1] = k_v; p.vv[2] = v_v;

    cudaFuncSetAttribute(proj_qkv, cudaFuncAttributeMaxDynamicSharedMemorySize, PROJ_SMEM);
    proj_qkv<<<dim3(6, NPIX / 128), 256, PROJ_SMEM>>>(
        p, xthi, xtlo, qthi, qtlo, gkp, gvp, qscale);

    // kp -> bf16 [patch][c]
    kconv_kernel<<<64, 256>>>(gkp, kpbh, kpbl);

    // attn via mma.sync
    cudaFuncSetAttribute(attn_mma, cudaFuncAttributeMaxDynamicSharedMemorySize, AT_SMEM);
    attn_mma<<<dim3(8, NUM), 256, AT_SMEM>>>(qthi, qtlo, kpbh, kpbl, ahi, alo);

    // flash v3
    cudaFuncSetAttribute(flash3_kernel, cudaFuncAttributeMaxDynamicSharedMemorySize, F_TOTAL);
    flash3_kernel<<<dim3(16, NUM), 256, F_TOTAL>>>(ahi, alo, gvp, pthi, ptlo);

    // o projection + residual -> d_out (bm fast -> L2 reuse of pthi/ptlo tiles)
    cudaFuncSetAttribute(proj_o<HALF>, cudaFuncAttributeMaxDynamicSharedMemorySize, PROJ_SMEM);
    proj_o<HALF><<<dim3(CIN / 128, NPIX / 128), 256, PROJ_SMEM>>>(
        whi[3], wlo[3], pthi, ptlo, o_g, o_b, o_m, o_v, out, x);
}

// round 17
// speedup vs baseline: 1.5082x; 1.0178x over previous
#include <cuda_runtime.h>
#include <cuda_bf16.h>
#include <cstdint>
#include <math.h>

#define HH 256
#define WW 256
#define NPIX 65536          // H*W
#define CIN 512
#define HALF 256
#define PSZ 32
#define NH 8
#define NUM 64              // patches
#define EPS 1e-5f

// ==================== mma.sync / ldmatrix / cp.async helpers ====================
__device__ __forceinline__ uint32_t smem_to_u32(const void* smem_ptr) {
    uint32_t addr;
    asm("{ .reg .u64 tmp; cvta.to.shared.u64 tmp, %1; cvt.u32.u64 %0, tmp; }"
        : "=r"(addr) : "l"(smem_ptr));
    return addr;
}
__device__ __forceinline__ void ldsm4(uint32_t* r, uint32_t addr) {
    asm volatile("ldmatrix.sync.aligned.m8n8.x4.shared.b16 {%0,%1,%2,%3}, [%4];"
        : "=r"(r[0]), "=r"(r[1]), "=r"(r[2]), "=r"(r[3]) : "r"(addr));
}
__device__ __forceinline__ void ldsm4t(uint32_t* r, uint32_t addr) {
    asm volatile("ldmatrix.sync.aligned.m8n8.x4.trans.shared.b16 {%0,%1,%2,%3}, [%4];"
        : "=r"(r[0]), "=r"(r[1]), "=r"(r[2]), "=r"(r[3]) : "r"(addr));
}
__device__ __forceinline__ void mma16816(float* c, const uint32_t* a, const uint32_t* b) {
    asm volatile(
        "mma.sync.aligned.m16n8k16.row.col.f32.bf16.bf16.f32 "
        "{%0,%1,%2,%3}, {%4,%5,%6,%7}, {%8,%9}, {%0,%1,%2,%3};"
        : "+f"(c[0]), "+f"(c[1]), "+f"(c[2]), "+f"(c[3])
        : "r"(a[0]), "r"(a[1]), "r"(a[2]), "r"(a[3]), "r"(b[0]), "r"(b[1]));
}
__device__ __forceinline__ uint32_t packbf2(float lo, float hi) {
    __nv_bfloat162 h = __floats2bfloat162_rn(lo, hi);
    return *(uint32_t*)&h;
}
__device__ __forceinline__ void cpasync16(uint32_t s, const void* g) {
    asm volatile("cp.async.cg.shared.global [%0], [%1], 16;" :: "r"(s), "l"(g) : "memory");
}
__device__ __forceinline__ void cpasync_commit() {
    asm volatile("cp.async.commit_group;" ::: "memory");
}
template <int N>
__device__ __forceinline__ void cpasync_wait() {
    asm volatile("cp.async.wait_group %0;" :: "n"(N) : "memory");
}

// ==================== static scratch ====================
__device__ __nv_bfloat16 g_xthi[(size_t)NPIX * CIN];   // x transposed hi, [pix][512]
__device__ __nv_bfloat16 g_xtlo[(size_t)NPIX * CIN];   // x transposed lo
__device__ __nv_bfloat16 g_qthi[(size_t)NPIX * HALF];  // q transposed hi, [pix][256]
__device__ __nv_bfloat16 g_qtlo[(size_t)NPIX * HALF];
__device__ __nv_bfloat16 g_pthi[(size_t)NPIX * HALF];  // attn-out transposed hi, [pix][256]
__device__ __nv_bfloat16 g_ptlo[(size_t)NPIX * HALF];
__device__ __nv_bfloat16 g_whi[4][CIN * HALF];         // q,k,v,o weights hi
__device__ __nv_bfloat16 g_wlo[4][CIN * HALF];
__device__ __nv_bfloat16 g_ahi[(size_t)NUM * 1024 * 64];   // attn bf16 hi
__device__ __nv_bfloat16 g_alo[(size_t)NUM * 1024 * 64];   // attn bf16 lo
__device__ float g_kp[HALF * NUM];                     // pooled k [c][patch] fp32
__device__ float g_vp[NUM * HALF];                     // pooled v [patch][c] fp32
__device__ __nv_bfloat16 g_kpbh[NUM * HALF];           // kp bf16 hi, [patch][c]
__device__ __nv_bfloat16 g_kpbl[NUM * HALF];           // kp bf16 lo

// ==================== conversion kernels ====================
__global__ void conv_w4_kernel(const float* __restrict__ w0, const float* __restrict__ w1,
                               const float* __restrict__ w2, const float* __restrict__ w3,
                               __nv_bfloat16* __restrict__ hi, __nv_bfloat16* __restrict__ lo)
{
    const int wsel = blockIdx.y;
    const float* w = (wsel == 0) ? w0 : (wsel == 1) ? w1 : (wsel == 2) ? w2 : w3;
    int i = blockIdx.x * 256 + threadIdx.x;
    float v = w[i];
    __nv_bfloat16 h = __float2bfloat16(v);
    const size_t off = (size_t)wsel * (CIN * HALF) + i;
    hi[off] = h;
    lo[off] = __float2bfloat16(v - __bfloat162float(h));
}

// x [512][NPIX] fp32 -> XT [NPIX][512] bf16 hi/lo  (32x32 tile transpose, packed stores)
__global__ void conv_x_kernel(const float* __restrict__ x,
                              __nv_bfloat16* __restrict__ hi,
                              __nv_bfloat16* __restrict__ lo)
{
    __shared__ float t[32][33];
    const int p0 = blockIdx.x * 32;
    const int k0 = blockIdx.y * 32;
    const int tx = threadIdx.x, ty = threadIdx.y;   // (32, 8)
    #pragma unroll
    for (int i = 0; i < 4; i++) {
        int kl = ty + i * 8;
        t[kl][tx] = x[(size_t)(k0 + kl) * NPIX + p0 + tx];
    }
    __syncthreads();
    const int txh = tx & 15;            // channel pair index
    const int po = (tx >> 4) * 8 + ty;  // 0..15
    #pragma unroll
    for (int i = 0; i < 2; i++) {
        const int pl = po + i * 16;
        float v0 = t[2 * txh][pl];
        float v1 = t[2 * txh + 1][pl];
        __nv_bfloat16 h0 = __float2bfloat16(v0);
        __nv_bfloat16 h1 = __float2bfloat16(v1);
        const size_t off = (size_t)(p0 + pl) * CIN + k0 + 2 * txh;
        *(uint32_t*)(hi + off) = packbf2(v0, v1);
        *(uint32_t*)(lo + off) = packbf2(v0 - __bfloat162float(h0), v1 - __bfloat162float(h1));
    }
}

__global__ void zero_pool_kernel(float* kp, float* vp)
{
    int i = blockIdx.x * 256 + threadIdx.x;   // grid 64 -> 16384
    kp[i] = 0.f;
    vp[i] = 0.f;
}

// kp [c][patch] fp32 -> [patch][c] bf16 hi/lo
__global__ void kconv_kernel(const float* __restrict__ kp,
                             __nv_bfloat16* __restrict__ kph, __nv_bfloat16* __restrict__ kpl)
{
    int i = blockIdx.x * 256 + threadIdx.x;   // grid 64 -> 16384
    const int patch = i >> 8;
    const int c = i & 255;
    float v = kp[c * NUM + patch];
    __nv_bfloat16 h = __float2bfloat16(v);
    kph[patch * HALF + c] = h;
    kpl[patch * HALF + c] = __float2bfloat16(v - __bfloat162float(h));
}

// ==================== fused q/k/v HMMA projection (grid = (6, 512)) ====================
#define LDKB2 80                      // 32 bf16 = 64B + 16B pad
#define TILE2 (128 * LDKB2)           // 10240
#define BUFSET (4 * TILE2)            // 40960
#define PROJ_SMEM (2 * BUFSET)        // 81920

struct QKVParams {
    const __nv_bfloat16* whi[3];
    const __nv_bfloat16* wlo[3];
    const float* gg[3];
    const float* bb[3];
    const float* mm[3];
    const float* vv[3];
};

__global__ void __launch_bounds__(256, 2)
proj_qkv(QKVParams p,
         const __nv_bfloat16* __restrict__ Bhi, const __nv_bfloat16* __restrict__ Blo,
         __nv_bfloat16* __restrict__ qhi, __nv_bfloat16* __restrict__ qlo,
         float* __restrict__ kpo, float* __restrict__ vpo, float qscale)
{
    extern __shared__ char smc[];
    const uint32_t sb = smem_to_u32(smc);

    const int tid = threadIdx.x;
    const int wid = tid >> 5;
    const int lane = tid & 31;
    const int wm = wid & 1;
    const int wn = wid >> 1;
    const int wsel = blockIdx.x >> 1;     // 0=q 1=k 2=v (fast index -> L2 reuse of x)
    const int bmh = blockIdx.x & 1;       // out-ch tile
    const int pixbase = blockIdx.y * 128;

    const __nv_bfloat16* Ahi = p.whi[wsel];
    const __nv_bfloat16* Alo = p.wlo[wsel];

    float acc[4][4][4];
    #pragma unroll
    for (int mt = 0; mt < 4; mt++)
        #pragma unroll
        for (int nt = 0; nt < 4; nt++)
            #pragma unroll
            for (int e = 0; e < 4; e++) acc[mt][nt][e] = 0.f;

    const int am_ = lane & 15;
    const int ak_ = (lane >> 4) * 8;
    const int bn_ = (lane & 7) + ((lane >> 4) << 3);
    const int bk_ = ((lane >> 3) & 1) * 8;

    const int lr[2] = { tid >> 2, (tid + 256) >> 2 };
    const int lc = tid & 3;

    const int NCH = CIN / 32;   // 16

    {
        #pragma unroll
        for (int j = 0; j < 2; j++) {
            const int r = lr[j];
            const size_t arow = (size_t)(bmh * 128 + r) * CIN + lc * 8;
            const size_t brow = (size_t)(pixbase + r) * CIN + lc * 8;
            cpasync16(sb + 0 * TILE2 + r * LDKB2 + lc * 16, Ahi + arow);
            cpasync16(sb + 1 * TILE2 + r * LDKB2 + lc * 16, Alo + arow);
            cpasync16(sb + 2 * TILE2 + r * LDKB2 + lc * 16, Bhi + brow);
            cpasync16(sb + 3 * TILE2 + r * LDKB2 + lc * 16, Blo + brow);
        }
        cpasync_commit();
    }

    for (int ch = 0; ch < NCH; ch++) {
        cpasync_wait<0>();
        __syncthreads();
        if (ch + 1 < NCH) {
            const uint32_t bufb = sb + ((ch + 1) & 1) * BUFSET;
            const int kc1 = (ch + 1) * 32;
            #pragma unroll
            for (int j = 0; j < 2; j++) {
                const int r = lr[j];
                const size_t arow = (size_t)(bmh * 128 + r) * CIN + kc1 + lc * 8;
                const size_t brow = (size_t)(pixbase + r) * CIN + kc1 + lc * 8;
                cpasync16(bufb + 0 * TILE2 + r * LDKB2 + lc * 16, Ahi + arow);
                cpasync16(bufb + 1 * TILE2 + r * LDKB2 + lc * 16, Alo + arow);
                cpasync16(bufb + 2 * TILE2 + r * LDKB2 + lc * 16, Bhi + brow);
                cpasync16(bufb + 3 * TILE2 + r * LDKB2 + lc * 16, Blo + brow);
            }
            cpasync_commit();
        }

        const uint32_t cb = sb + (ch & 1) * BUFSET;
        const uint32_t bAh = cb, bAl = cb + TILE2, bBh = cb + 2 * TILE2, bBl = cb + 3 * TILE2;
        #pragma unroll
        for (int ks = 0; ks < 2; ks++) {
            const int kc = ks * 16;
            uint32_t a[4][4], bh[4][2], bl[4][2];
            #pragma unroll
            for (int mt = 0; mt < 4; mt++)
                ldsm4(a[mt], bAh + (wm * 64 + mt * 16 + am_) * LDKB2 + (kc + ak_) * 2);
            #pragma unroll
            for (int pr = 0; pr < 2; pr++) {
                uint32_t r4[4];
                ldsm4(r4, bBh + (wn * 32 + pr * 16 + bn_) * LDKB2 + (kc + bk_) * 2);
                bh[2 * pr][0] = r4[0]; bh[2 * pr][1] = r4[1];
                bh[2 * pr + 1][0] = r4[2]; bh[2 * pr + 1][1] = r4[3];
            }
            #pragma unroll
            for (int mt = 0; mt < 4; mt++)
                #pragma unroll
                for (int nt = 0; nt < 4; nt++) mma16816(acc[mt][nt], a[mt], bh[nt]);
            #pragma unroll
            for (int pr = 0; pr < 2; pr++) {
                uint32_t r4[4];
                ldsm4(r4, bBl + (wn * 32 + pr * 16 + bn_) * LDKB2 + (kc + bk_) * 2);
                bl[2 * pr][0] = r4[0]; bl[2 * pr][1] = r4[1];
                bl[2 * pr + 1][0] = r4[2]; bl[2 * pr + 1][1] = r4[3];
            }
            #pragma unroll
            for (int mt = 0; mt < 4; mt++)
                #pragma unroll
                for (int nt = 0; nt < 4; nt++) mma16816(acc[mt][nt], a[mt], bl[nt]);
            #pragma unroll
            for (int mt = 0; mt < 4; mt++)
                ldsm4(a[mt], bAl + (wm * 64 + mt * 16 + am_) * LDKB2 + (kc + ak_) * 2);
            #pragma unroll
            for (int mt = 0; mt < 4; mt++)
                #pragma unroll
                for (int nt = 0; nt < 4; nt++) mma16816(acc[mt][nt], a[mt], bh[nt]);
        }
    }
    __syncthreads();

    if (wsel >= 1) {
        const int x0 = (pixbase & 255) + wn * 32;
        const int y0 = pixbase >> 8;
        const int patch = ((y0 >> 5) << 3) + (x0 >> 5);
        const float inv = 1.f / 1024.f;
        const float* gg = p.gg[wsel];
        const float* bb = p.bb[wsel];
        const float* mm = p.mm[wsel];
        const float* vv = p.vv[wsel];
        float* outp = (wsel == 1) ? kpo : vpo;
        #pragma unroll
        for (int mt = 0; mt < 4; mt++) {
            #pragma unroll
            for (int hf = 0; hf < 2; hf++) {
                const int o = bmh * 128 + wm * 64 + mt * 16 + (lane >> 2) + hf * 8;
                const float s_r = gg[o] * rsqrtf(vv[o] + EPS);
                const float t_r = bb[o] - mm[o] * s_r;
                float s = 0.f;
                #pragma unroll
                for (int nt = 0; nt < 4; nt++) {
                    s += fmaxf(acc[mt][nt][2 * hf + 0] * s_r + t_r, 0.f);
                    s += fmaxf(acc[mt][nt][2 * hf + 1] * s_r + t_r, 0.f);
                }
                s += __shfl_xor_sync(0xffffffffu, s, 1);
                s += __shfl_xor_sync(0xffffffffu, s, 2);
                if ((lane & 3) == 0) {
                    if (wsel == 1) atomicAdd(outp + o * NUM + patch, s * inv);
                    else           atomicAdd(outp + patch * HALF + o, s * inv);
                }
            }
        }
    } else {
        float* stage = (float*)smc;                  // 128 x 131 fp32
        float* scb = (float*)(smc + 68608);
        float* bob = (float*)(smc + 69632);
        if (tid < 128) {
            const int o = bmh * 128 + tid;
            const float s_r = p.gg[0][o] * rsqrtf(p.vv[0][o] + EPS);
            scb[tid] = s_r;
            bob[tid] = p.bb[0][o] - p.mm[0][o] * s_r;
        }
        __syncthreads();
        #pragma unroll
        for (int mt = 0; mt < 4; mt++) {
            const int r_lo = wm * 64 + mt * 16 + (lane >> 2);
            #pragma unroll
            for (int nt = 0; nt < 4; nt++) {
                const int c = wn * 32 + nt * 8 + (lane & 3) * 2;
                stage[r_lo * 131 + c]     = fmaxf(acc[mt][nt][0] * scb[r_lo] + bob[r_lo], 0.f) * qscale;
                stage[r_lo * 131 + c + 1] = fmaxf(acc[mt][nt][1] * scb[r_lo] + bob[r_lo], 0.f) * qscale;
                stage[(r_lo + 8) * 131 + c]     = fmaxf(acc[mt][nt][2] * scb[r_lo + 8] + bob[r_lo + 8], 0.f) * qscale;
                stage[(r_lo + 8) * 131 + c + 1] = fmaxf(acc[mt][nt][3] * scb[r_lo + 8] + bob[r_lo + 8], 0.f) * qscale;
            }
        }
        __syncthreads();
        for (int i = tid; i < 128 * 64; i += 256) {
            const int pixl = i >> 6;
            const int cp = (i & 63) * 2;
            float v0 = stage[cp * 131 + pixl];
            float v1 = stage[(cp + 1) * 131 + pixl];
            __nv_bfloat16 h0 = __float2bfloat16(v0);
            __nv_bfloat16 h1 = __float2bfloat16(v1);
            const size_t off = (size_t)(pixbase + pixl) * HALF + bmh * 128 + cp;
            *(uint32_t*)(qhi + off) = packbf2(v0, v1);
            *(uint32_t*)(qlo + off) = packbf2(v0 - __bfloat162float(h0), v1 - __bfloat162float(h1));
        }
    }
}

// ==================== HMMA o-projection (grid = (4, 512)) ====================
template <int KDIM>
__global__ void __launch_bounds__(256, 2)
proj_o(const __nv_bfloat16* __restrict__ Ahi, const __nv_bfloat16* __restrict__ Alo,
       const __nv_bfloat16* __restrict__ Bhi, const __nv_bfloat16* __restrict__ Blo,
       const float* __restrict__ gg, const float* __restrict__ bb,
       const float* __restrict__ mm, const float* __restrict__ vv,
       float* __restrict__ outp, const float* __restrict__ resid)
{
    extern __shared__ char smc[];
    const uint32_t sb = smem_to_u32(smc);

    const int tid = threadIdx.x;
    const int wid = tid >> 5;
    const int lane = tid & 31;
    const int wm = wid & 1;
    const int wn = wid >> 1;
    const int bm = blockIdx.x;
    const int pixbase = blockIdx.y * 128;

    float acc[4][4][4];
    #pragma unroll
    for (int mt = 0; mt < 4; mt++)
        #pragma unroll
        for (int nt = 0; nt < 4; nt++)
            #pragma unroll
            for (int e = 0; e < 4; e++) acc[mt][nt][e] = 0.f;

    const int am_ = lane & 15;
    const int ak_ = (lane >> 4) * 8;
    const int bn_ = (lane & 7) + ((lane >> 4) << 3);
    const int bk_ = ((lane >> 3) & 1) * 8;

    const int lr[2] = { tid >> 2, (tid + 256) >> 2 };
    const int lc = tid & 3;

    const int NCH = KDIM / 32;

    {
        #pragma unroll
        for (int j = 0; j < 2; j++) {
            const int r = lr[j];
            const size_t arow = (size_t)(bm * 128 + r) * KDIM + lc * 8;
            const size_t brow = (size_t)(pixbase + r) * KDIM + lc * 8;
            cpasync16(sb + 0 * TILE2 + r * LDKB2 + lc * 16, Ahi + arow);
            cpasync16(sb + 1 * TILE2 + r * LDKB2 + lc * 16, Alo + arow);
            cpasync16(sb + 2 * TILE2 + r * LDKB2 + lc * 16, Bhi + brow);
            cpasync16(sb + 3 * TILE2 + r * LDKB2 + lc * 16, Blo + brow);
        }
        cpasync_commit();
    }

    for (int ch = 0; ch < NCH; ch++) {
        cpasync_wait<0>();
        __syncthreads();
        if (ch + 1 < NCH) {
            const uint32_t bufb = sb + ((ch + 1) & 1) * BUFSET;
            const int kc1 = (ch + 1) * 32;
            #pragma unroll
            for (int j = 0; j < 2; j++) {
                const int r = lr[j];
                const size_t arow = (size_t)(bm * 128 + r) * KDIM + kc1 + lc * 8;
                const size_t brow = (size_t)(pixbase + r) * KDIM + kc1 + lc * 8;
                cpasync16(bufb + 0 * TILE2 + r * LDKB2 + lc * 16, Ahi + arow);
                cpasync16(bufb + 1 * TILE2 + r * LDKB2 + lc * 16, Alo + arow);
                cpasync16(bufb + 2 * TILE2 + r * LDKB2 + lc * 16, Bhi + brow);
                cpasync16(bufb + 3 * TILE2 + r * LDKB2 + lc * 16, Blo + brow);
            }
            cpasync_commit();
        }

        const uint32_t cb = sb + (ch & 1) * BUFSET;
        const uint32_t bAh = cb, bAl = cb + TILE2, bBh = cb + 2 * TILE2, bBl = cb + 3 * TILE2;
        #pragma unroll
        for (int ks = 0; ks < 2; ks++) {
            const int kc = ks * 16;
            uint32_t a[4][4], bh[4][2], bl[4][2];
            #pragma unroll
            for (int mt = 0; mt < 4; mt++)
                ldsm4(a[mt], bAh + (wm * 64 + mt * 16 + am_) * LDKB2 + (kc + ak_) * 2);
            #pragma unroll
            for (int pr = 0; pr < 2; pr++) {
                uint32_t r4[4];
                ldsm4(r4, bBh + (wn * 32 + pr * 16 + bn_) * LDKB2 + (kc + bk_) * 2);
                bh[2 * pr][0] = r4[0]; bh[2 * pr][1] = r4[1];
                bh[2 * pr + 1][0] = r4[2]; bh[2 * pr + 1][1] = r4[3];
            }
            #pragma unroll
            for (int mt = 0; mt < 4; mt++)
                #pragma unroll
                for (int nt = 0; nt < 4; nt++) mma16816(acc[mt][nt], a[mt], bh[nt]);
            #pragma unroll
            for (int pr = 0; pr < 2; pr++) {
                uint32_t r4[4];
                ldsm4(r4, bBl + (wn * 32 + pr * 16 + bn_) * LDKB2 + (kc + bk_) * 2);
                bl[2 * pr][0] = r4[0]; bl[2 * pr][1] = r4[1];
                bl[2 * pr + 1][0] = r4[2]; bl[2 * pr + 1][1] = r4[3];
            }
            #pragma unroll
            for (int mt = 0; mt < 4; mt++)
                #pragma unroll
                for (int nt = 0; nt < 4; nt++) mma16816(acc[mt][nt], a[mt], bl[nt]);
            #pragma unroll
            for (int mt = 0; mt < 4; mt++)
                ldsm4(a[mt], bAl + (wm * 64 + mt * 16 + am_) * LDKB2 + (kc + ak_) * 2);
            #pragma unroll
            for (int mt = 0; mt < 4; mt++)
                #pragma unroll
                for (int nt = 0; nt < 4; nt++) mma16816(acc[mt][nt], a[mt], bh[nt]);
        }
    }
    __syncthreads();

    float* stage = (float*)smc;
    float* scb = (float*)(smc + 68608);
    float* bob = (float*)(smc + 69632);
    if (tid < 128) {
        const int o = bm * 128 + tid;
        const float s_r = gg[o] * rsqrtf(vv[o] + EPS);
        scb[tid] = s_r;
        bob[tid] = bb[o] - mm[o] * s_r;
    }
    __syncthreads();
    #pragma unroll
    for (int mt = 0; mt < 4; mt++) {
        const int r_lo = wm * 64 + mt * 16 + (lane >> 2);
        #pragma unroll
        for (int nt = 0; nt < 4; nt++) {
            const int c = wn * 32 + nt * 8 + (lane & 3) * 2;
            stage[r_lo * 130 + c]     = fmaxf(acc[mt][nt][0] * scb[r_lo] + bob[r_lo], 0.f);
            stage[r_lo * 130 + c + 1] = fmaxf(acc[mt][nt][1] * scb[r_lo] + bob[r_lo], 0.f);
            stage[(r_lo + 8) * 130 + c]     = fmaxf(acc[mt][nt][2] * scb[r_lo + 8] + bob[r_lo + 8], 0.f);
            stage[(r_lo + 8) * 130 + c + 1] = fmaxf(acc[mt][nt][3] * scb[r_lo + 8] + bob[r_lo + 8], 0.f);
        }
    }
    __syncthreads();
    for (int i = tid; i < 128 * 128; i += 256) {
        const int r = i >> 7;
        const int c = i & 127;
        const size_t go = (size_t)(bm * 128 + r) * NPIX + pixbase + c;
        outp[go] = stage[r * 130 + c] + resid[go];
    }
}

// ==================== attn via mma.sync ====================
#define AT_KPH 0
#define AT_KPSTR 528
#define AT_KPL (64 * AT_KPSTR)          // 33792
#define AT_QB  (2 * 64 * AT_KPSTR)      // 67584
#define AT_QBSZ (2 * 128 * LDKB2)       // 20480
#define AT_SMEM (AT_QB + 2 * AT_QBSZ)   // 108544
__global__ void __launch_bounds__(256, 2)
attn_mma(const __nv_bfloat16* __restrict__ qhi, const __nv_bfloat16* __restrict__ qlo,
         const __nv_bfloat16* __restrict__ kph, const __nv_bfloat16* __restrict__ kpl,
         __nv_bfloat16* __restrict__ ahi, __nv_bfloat16* __restrict__ alo)
{
    extern __shared__ char smc[];
    const uint32_t sb = smem_to_u32(smc);

    const int rowblk = blockIdx.x;
    const int b = blockIdx.y;
    const int tid = threadIdx.x;
    const int wid = tid >> 5;
    const int lane = tid & 31;
    const int ph = b >> 3, pw = b & 7;
    const int pixbase = ph * 32 * WW + pw * 32;

    #pragma unroll
    for (int j = 0; j < 8; j++) {
        const int idx = tid + j * 256;
        const int r = idx >> 5;
        const int c16 = idx & 31;
        *(uint4*)(smc + AT_KPH + r * AT_KPSTR + c16 * 16) = *(const uint4*)(kph + r * HALF + c16 * 8);
        *(uint4*)(smc + AT_KPL + r * AT_KPSTR + c16 * 16) = *(const uint4*)(kpl + r * HALF + c16 * 8);
    }

    const int qr[2] = { tid >> 2, (tid + 256) >> 2 };
    const int qc = tid & 3;
    int qpix[2];
    #pragma unroll
    for (int j = 0; j < 2; j++) {
        const int n = rowblk * 128 + qr[j];
        qpix[j] = pixbase + (n >> 5) * WW + (n & 31);
    }

    {
        const uint32_t qb = sb + AT_QB;
        #pragma unroll
        for (int j = 0; j < 2; j++) {
            const size_t g = (size_t)qpix[j] * HALF + qc * 8;
            cpasync16(qb + qr[j] * LDKB2 + qc * 16, qhi + g);
            cpasync16(qb + 128 * LDKB2 + qr[j] * LDKB2 + qc * 16, qlo + g);
        }
        cpasync_commit();
    }

    const int am_ = lane & 15;
    const int ak_ = (lane >> 4) * 8;
    const int bn_ = (lane & 7) + ((lane >> 4) << 3);
    const int bk_ = ((lane >> 3) & 1) * 8;
    const int grp = lane >> 2;
    const int qd = lane & 3;

    float S[8][4];
    #pragma unroll
    for (int nt = 0; nt < 8; nt++)
        #pragma unroll
        for (int e = 0; e < 4; e++) S[nt][e] = 0.f;

    const int NCH = HALF / 32;   // 8
    for (int ch = 0; ch < NCH; ch++) {
        cpasync_wait<0>();
        __syncthreads();
        if (ch + 1 < NCH) {
            const uint32_t qb = sb + AT_QB + ((ch + 1) & 1) * AT_QBSZ;
            const int kc1 = (ch + 1) * 32;
            #pragma unroll
            for (int j = 0; j < 2; j++) {
                const size_t g = (size_t)qpix[j] * HALF + kc1 + qc * 8;
                cpasync16(qb + qr[j] * LDKB2 + qc * 16, qhi + g);
                cpasync16(qb + 128 * LDKB2 + qr[j] * LDKB2 + qc * 16, qlo + g);
            }
            cpasync_commit();
        }

        const uint32_t qb = sb + AT_QB + (ch & 1) * AT_QBSZ;
        const uint32_t qHI = qb, qLO = qb + 128 * LDKB2;
        #pragma unroll
        for (int ks = 0; ks < 2; ks++) {
            const int kc = ks * 16;
            const int kb = (ch * 32 + kc) * 2;
            uint32_t a[4], bh[8][2], bl[8][2];
            ldsm4(a, qHI + (wid * 16 + am_) * LDKB2 + (kc + ak_) * 2);
            #pragma unroll
            for (int pr = 0; pr < 4; pr++) {
                uint32_t r4[4];
                ldsm4(r4, sb + AT_KPH + (pr * 16 + bn_) * AT_KPSTR + kb + bk_ * 2);
                bh[2 * pr][0] = r4[0]; bh[2 * pr][1] = r4[1];
                bh[2 * pr + 1][0] = r4[2]; bh[2 * pr + 1][1] = r4[3];
            }
            #pragma unroll
            for (int nt = 0; nt < 8; nt++) mma16816(S[nt], a, bh[nt]);
            #pragma unroll
            for (int pr = 0; pr < 4; pr++) {
                uint32_t r4[4];
                ldsm4(r4, sb + AT_KPL + (pr * 16 + bn_) * AT_KPSTR + kb + bk_ * 2);
                bl[2 * pr][0] = r4[0]; bl[2 * pr][1] = r4[1];
                bl[2 * pr + 1][0] = r4[2]; bl[2 * pr + 1][1] = r4[3];
            }
            #pragma unroll
            for (int nt = 0; nt < 8; nt++) mma16816(S[nt], a, bl[nt]);
            ldsm4(a, qLO + (wid * 16 + am_) * LDKB2 + (kc + ak_) * 2);
            #pragma unroll
            for (int nt = 0; nt < 8; nt++) mma16816(S[nt], a, bh[nt]);
        }
    }

    const int r1 = wid * 16 + grp;
    #pragma unroll
    for (int nt = 0; nt < 8; nt++) {
        const int col = nt * 8 + qd * 2;
        {
            const int n = rowblk * 128 + r1;
            const size_t off = ((size_t)b * 1024 + n) * 64 + col;
            float v0 = S[nt][0], v1 = S[nt][1];
            __nv_bfloat16 h0 = __float2bfloat16(v0);
            __nv_bfloat16 h1 = __float2bfloat16(v1);
            *(uint32_t*)(ahi + off) = packbf2(v0, v1);
            *(uint32_t*)(alo + off) = packbf2(v0 - __bfloat162float(h0), v1 - __bfloat162float(h1));
        }
        {
            const int n = rowblk * 128 + r1 + 8;
            const size_t off = ((size_t)b * 1024 + n) * 64 + col;
            float v0 = S[nt][2], v1 = S[nt][3];
            __nv_bfloat16 h0 = __float2bfloat16(v0);
            __nv_bfloat16 h1 = __float2bfloat16(v1);
            *(uint32_t*)(ahi + off) = packbf2(v0, v1);
            *(uint32_t*)(alo + off) = packbf2(v0 - __bfloat162float(h0), v1 - __bfloat162float(h1));
        }
    }
}

// ==================== flash v4: warp-local nested-softmax attention ====================
// Block = (128-row chunk, patch), 8 warps; each warp owns 16 rows x all 64 cols x full k.
// Softmax state in registers (quad-replicated); 1 barrier per K tile.
#define F4LDB 144
#define F4_QHI 0                // 128*144 = 18432
#define F4_QLO 18432
#define F4_KB  36864            // + buf*18432; kHI +0, kLO +9216
#define F4_TOTAL 73728
__global__ void __launch_bounds__(256, 2)
flash4_kernel(const __nv_bfloat16* __restrict__ ahi, const __nv_bfloat16* __restrict__ alo,
              const float* __restrict__ vp,
              __nv_bfloat16* __restrict__ pthi, __nv_bfloat16* __restrict__ ptlo)
{
    extern __shared__ char smc[];
    const uint32_t sb = smem_to_u32(smc);

    const int rblk = blockIdx.x;    // 0..7, 128 rows each
    const int b = blockIdx.y;       // patch
    const int tid = threadIdx.x;
    const int lane = tid & 31;
    const int wid = tid >> 5;       // warp owns rows wid*16 .. +15
    const int r0 = rblk * 128;
    const size_t abase = (size_t)b * 1024 * 64;

    // K tile 0 via cp.async
    const int kr[2] = { tid >> 3, (tid + 256) >> 3 };
    const int kc_ = tid & 7;
    {
        const uint32_t kb = sb + F4_KB;
        #pragma unroll
        for (int j = 0; j < 2; j++) {
            const size_t g = abase + (size_t)kr[j] * 64 + kc_ * 8;
            cpasync16(kb + kr[j] * F4LDB + kc_ * 16, ahi + g);
            cpasync16(kb + 9216 + kr[j] * F4LDB + kc_ * 16, alo + g);
        }
        cpasync_commit();
    }
    // Q tile (128 rows) plain loads, overlapping K0 flight
    #pragma unroll
    for (int i = 0; i < 4; i++) {
        const int idx = tid + i * 256;
        const int r = idx >> 3;
        const int c = idx & 7;
        const size_t g = abase + (size_t)(r0 + r) * 64 + c * 8;
        *(uint4*)(smc + F4_QHI + r * F4LDB + c * 16) = *(const uint4*)(ahi + g);
        *(uint4*)(smc + F4_QLO + r * F4LDB + c * 16) = *(const uint4*)(alo + g);
    }

    const int am_ = lane & 15;
    const int ak_ = (lane >> 4) * 8;
    const int bn_ = (lane & 7) + ((lane >> 4) << 3);
    const int bk_ = ((lane >> 3) & 1) * 8;
    const int vk_ = lane & 15;
    const int vn_ = (lane >> 4) << 3;
    const int grp = lane >> 2;
    const int qd  = lane & 3;

    float O[8][4];
    #pragma unroll
    for (int nt = 0; nt < 8; nt++)
        #pragma unroll
        for (int e = 0; e < 4; e++) O[nt][e] = 0.f;
    float m0 = -1e30f, m1 = -1e30f, l0 = 0.f, l1 = 0.f;

    for (int t = 0; t < 16; t++) {
        cpasync_wait<0>();
        __syncthreads();          // tile t + Q visible; all warps done with other buffer
        if (t + 1 < 16) {
            const uint32_t kb = sb + F4_KB + ((t + 1) & 1) * 18432;
            #pragma unroll
            for (int j = 0; j < 2; j++) {
                const size_t g = abase + (size_t)((t + 1) * 64 + kr[j]) * 64 + kc_ * 8;
                cpasync16(kb + kr[j] * F4LDB + kc_ * 16, ahi + g);
                cpasync16(kb + 9216 + kr[j] * F4LDB + kc_ * 16, alo + g);
            }
            cpasync_commit();
        }
        const uint32_t kb = sb + F4_KB + (t & 1) * 18432;
        const uint32_t kHI = kb, kLO = kb + 9216;

        // ---- GEMM1: S(16 x 64) = Q K^T (3-term split) ----
        float S[8][4];
        #pragma unroll
        for (int nt = 0; nt < 8; nt++)
            #pragma unroll
            for (int e = 0; e < 4; e++) S[nt][e] = 0.f;
        #pragma unroll
        for (int kc = 0; kc < 4; kc++) {
            uint32_t aq[4], bh[8][2], bl[8][2];
            ldsm4(aq, sb + F4_QHI + (wid * 16 + am_) * F4LDB + (kc * 16 + ak_) * 2);
            #pragma unroll
            for (int ng = 0; ng < 4; ng++) {
                uint32_t r4[4];
                ldsm4(r4, kHI + (ng * 16 + bn_) * F4LDB + (kc * 16 + bk_) * 2);
                bh[2 * ng][0] = r4[0]; bh[2 * ng][1] = r4[1];
                bh[2 * ng + 1][0] = r4[2]; bh[2 * ng + 1][1] = r4[3];
            }
            #pragma unroll
            for (int nt = 0; nt < 8; nt++) mma16816(S[nt], aq, bh[nt]);
            #pragma unroll
            for (int ng = 0; ng < 4; ng++) {
                uint32_t r4[4];
                ldsm4(r4, kLO + (ng * 16 + bn_) * F4LDB + (kc * 16 + bk_) * 2);
                bl[2 * ng][0] = r4[0]; bl[2 * ng][1] = r4[1];
                bl[2 * ng + 1][0] = r4[2]; bl[2 * ng + 1][1] = r4[3];
            }
            #pragma unroll
            for (int nt = 0; nt < 8; nt++) mma16816(S[nt], aq, bl[nt]);
            ldsm4(aq, sb + F4_QLO + (wid * 16 + am_) * F4LDB + (kc * 16 + ak_) * 2);
            #pragma unroll
            for (int nt = 0; nt < 8; nt++) mma16816(S[nt], aq, bh[nt]);
        }

        // ---- warp-local online softmax (rows grp and grp+8 per quad) ----
        float la = -1e30f, lb = -1e30f;
        #pragma unroll
        for (int nt = 0; nt < 8; nt++) {
            la = fmaxf(la, fmaxf(S[nt][0], S[nt][1]));
            lb = fmaxf(lb, fmaxf(S[nt][2], S[nt][3]));
        }
        la = fmaxf(la, __shfl_xor_sync(0xffffffffu, la, 1));
        la = fmaxf(la, __shfl_xor_sync(0xffffffffu, la, 2));
        lb = fmaxf(lb, __shfl_xor_sync(0xffffffffu, lb, 1));
        lb = fmaxf(lb, __shfl_xor_sync(0xffffffffu, lb, 2));
        const float mn0 = fmaxf(m0, la);
        const float mn1 = fmaxf(m1, lb);
        const float sc0 = __expf(m0 - mn0);
        const float sc1 = __expf(m1 - mn1);
        m0 = mn0; m1 = mn1;
        float ra = 0.f, rb = 0.f;
        #pragma unroll
        for (int nt = 0; nt < 8; nt++) {
            S[nt][0] = __expf(S[nt][0] - mn0);
            S[nt][1] = __expf(S[nt][1] - mn0);
            S[nt][2] = __expf(S[nt][2] - mn1);
            S[nt][3] = __expf(S[nt][3] - mn1);
            ra += S[nt][0] + S[nt][1];
            rb += S[nt][2] + S[nt][3];
        }
        ra += __shfl_xor_sync(0xffffffffu, ra, 1);
        ra += __shfl_xor_sync(0xffffffffu, ra, 2);
        rb += __shfl_xor_sync(0xffffffffu, rb, 1);
        rb += __shfl_xor_sync(0xffffffffu, rb, 2);
        l0 = l0 * sc0 + ra;
        l1 = l1 * sc1 + rb;
        #pragma unroll
        for (int nt = 0; nt < 8; nt++) {
            O[nt][0] *= sc0; O[nt][1] *= sc0;
            O[nt][2] *= sc1; O[nt][3] *= sc1;
        }

        // ---- GEMM2: O(16 x 64) += P V (3-term split) ----
        #pragma unroll
        for (int kc = 0; kc < 4; kc++) {
            uint32_t aPh[4], aPl[4];
            aPh[0] = packbf2(S[2 * kc][0], S[2 * kc][1]);
            aPh[1] = packbf2(S[2 * kc][2], S[2 * kc][3]);
            aPh[2] = packbf2(S[2 * kc + 1][0], S[2 * kc + 1][1]);
            aPh[3] = packbf2(S[2 * kc + 1][2], S[2 * kc + 1][3]);
            {
                float p00 = S[2 * kc][0] - __bfloat162float(__float2bfloat16(S[2 * kc][0]));
                float p01 = S[2 * kc][1] - __bfloat162float(__float2bfloat16(S[2 * kc][1]));
                float p02 = S[2 * kc][2] - __bfloat162float(__float2bfloat16(S[2 * kc][2]));
                float p03 = S[2 * kc][3] - __bfloat162float(__float2bfloat16(S[2 * kc][3]));
                float p10 = S[2 * kc + 1][0] - __bfloat162float(__float2bfloat16(S[2 * kc + 1][0]));
                float p11 = S[2 * kc + 1][1] - __bfloat162float(__float2bfloat16(S[2 * kc + 1][1]));
                float p12 = S[2 * kc + 1][2] - __bfloat162float(__float2bfloat16(S[2 * kc + 1][2]));
                float p13 = S[2 * kc + 1][3] - __bfloat162float(__float2bfloat16(S[2 * kc + 1][3]));
                aPl[0] = packbf2(p00, p01);
                aPl[1] = packbf2(p02, p03);
                aPl[2] = packbf2(p10, p11);
                aPl[3] = packbf2(p12, p13);
            }
            #pragma unroll
            for (int ng = 0; ng < 4; ng++) {
                uint32_t vh[4], vl[4];
                ldsm4t(vh, kHI + (kc * 16 + vk_) * F4LDB + (ng * 16 + vn_) * 2);
                ldsm4t(vl, kLO + (kc * 16 + vk_) * F4LDB + (ng * 16 + vn_) * 2);
                uint32_t b0h[2] = { vh[0], vh[1] }, b1h[2] = { vh[2], vh[3] };
                uint32_t b0l[2] = { vl[0], vl[1] }, b1l[2] = { vl[2], vl[3] };
                mma16816(O[2 * ng + 0], aPh, b0h);
                mma16816(O[2 * ng + 1], aPh, b1h);
                mma16816(O[2 * ng + 0], aPh, b0l);
                mma16816(O[2 * ng + 1], aPh, b1l);
                mma16816(O[2 * ng + 0], aPl, b0h);
                mma16816(O[2 * ng + 1], aPl, b1h);
            }
        }
    }

    // ---- final: fv = A + O/l, warp-local softmax over 64 cols ----
    const int row0 = wid * 16 + grp;
    const int row1 = row0 + 8;
    const float il0 = 1.f / l0, il1 = 1.f / l1;
    float fv[8][4];
    #pragma unroll
    for (int nt = 0; nt < 8; nt++) {
        const int col = nt * 8 + qd * 2;
        uint32_t qh0 = *(uint32_t*)(smc + F4_QHI + row0 * F4LDB + col * 2);
        uint32_t ql0 = *(uint32_t*)(smc + F4_QLO + row0 * F4LDB + col * 2);
        uint32_t qh1 = *(uint32_t*)(smc + F4_QHI + row1 * F4LDB + col * 2);
        uint32_t ql1 = *(uint32_t*)(smc + F4_QLO + row1 * F4LDB + col * 2);
        __nv_bfloat162 h0 = *(__nv_bfloat162*)&qh0;
        __nv_bfloat162 g0 = *(__nv_bfloat162*)&ql0;
        __nv_bfloat162 h1 = *(__nv_bfloat162*)&qh1;
        __nv_bfloat162 g1 = *(__nv_bfloat162*)&ql1;
        fv[nt][0] = __bfloat162float(h0.x) + __bfloat162float(g0.x) + O[nt][0] * il0;
        fv[nt][1] = __bfloat162float(h0.y) + __bfloat162float(g0.y) + O[nt][1] * il0;
        fv[nt][2] = __bfloat162float(h1.x) + __bfloat162float(g1.x) + O[nt][2] * il1;
        fv[nt][3] = __bfloat162float(h1.y) + __bfloat162float(g1.y) + O[nt][3] * il1;
    }
    float fm0 = -1e30f, fm1 = -1e30f;
    #pragma unroll
    for (int nt = 0; nt < 8; nt++) {
        fm0 = fmaxf(fm0, fmaxf(fv[nt][0], fv[nt][1]));
        fm1 = fmaxf(fm1, fmaxf(fv[nt][2], fv[nt][3]));
    }
    fm0 = fmaxf(fm0, __shfl_xor_sync(0xffffffffu, fm0, 1));
    fm0 = fmaxf(fm0, __shfl_xor_sync(0xffffffffu, fm0, 2));
    fm1 = fmaxf(fm1, __shfl_xor_sync(0xffffffffu, fm1, 1));
    fm1 = fmaxf(fm1, __shfl_xor_sync(0xffffffffu, fm1, 2));
    float fs0 = 0.f, fs1 = 0.f;
    #pragma unroll
    for (int nt = 0; nt < 8; nt++) {
        fv[nt][0] = __expf(fv[nt][0] - fm0);
        fv[nt][1] = __expf(fv[nt][1] - fm0);
        fv[nt][2] = __expf(fv[nt][2] - fm1);
        fv[nt][3] = __expf(fv[nt][3] - fm1);
        fs0 += fv[nt][0] + fv[nt][1];
        fs1 += fv[nt][2] + fv[nt][3];
    }
    fs0 += __shfl_xor_sync(0xffffffffu, fs0, 1);
    fs0 += __shfl_xor_sync(0xffffffffu, fs0, 2);
    fs1 += __shfl_xor_sync(0xffffffffu, fs1, 1);
    fs1 += __shfl_xor_sync(0xffffffffu, fs1, 2);
    const float is0 = 1.f / fs0, is1 = 1.f / fs1;

    __syncthreads();              // all fv reads of Q done before Ps overlays it
    float* Ps = (float*)smc;      // [128][68] fp32 = 34816 (overlays Q region)
    #pragma unroll
    for (int nt = 0; nt < 8; nt++) {
        const int col = nt * 8 + qd * 2;
        Ps[row0 * 68 + col]     = fv[nt][0] * is0;
        Ps[row0 * 68 + col + 1] = fv[nt][1] * is0;
        Ps[row1 * 68 + col]     = fv[nt][2] * is1;
        Ps[row1 * 68 + col + 1] = fv[nt][3] * is1;
    }
    __syncthreads();

    // ---- out GEMM: two 64-row halves; staged transposed bf16 hi/lo store ----
    const int txx = tid & 15;
    const int tyy = tid >> 4;
    const int ph = b >> 3, pw = b & 7;
    const int pixbase = ph * 32 * WW + pw * 32;
    float* stg = (float*)(smc + F4_KB);    // [64][65] fp32 (K buffers dead)

    #pragma unroll 1
    for (int half = 0; half < 2; half++) {
        float acc[4][16];
        #pragma unroll
        for (int i = 0; i < 4; i++)
            #pragma unroll
            for (int j = 0; j < 16; j++) acc[i][j] = 0.f;
        #pragma unroll 2
        for (int m = 0; m < 64; m++) {
            float pr[4];
            #pragma unroll
            for (int i = 0; i < 4; i++) pr[i] = Ps[(half * 64 + tyy * 4 + i) * 68 + m];
            const float4* vr = (const float4*)(vp + m * 256 + txx * 16);
            float4 v0 = vr[0], v1 = vr[1], v2 = vr[2], v3 = vr[3];
            const float vw[16] = {v0.x, v0.y, v0.z, v0.w, v1.x, v1.y, v1.z, v1.w,
                                  v2.x, v2.y, v2.z, v2.w, v3.x, v3.y, v3.z, v3.w};
            #pragma unroll
            for (int i = 0; i < 4; i++)
                #pragma unroll
                for (int j = 0; j < 16; j++) acc[i][j] += pr[i] * vw[j];
        }
        #pragma unroll 1
        for (int g = 0; g < 4; g++) {
            __syncthreads();
            if ((txx >> 2) == g) {
                const int txl = txx & 3;
                #pragma unroll
                for (int i = 0; i < 4; i++)
                    #pragma unroll
                    for (int j = 0; j < 16; j++)
                        stg[(tyy * 4 + i) * 65 + txl * 16 + j] = acc[i][j];
            }
            __syncthreads();
            const int rl = tid >> 2;
            const int cc0 = (tid & 3) * 16;
            const int n = r0 + half * 64 + rl;
            const int pix = pixbase + (n >> 5) * WW + (n & 31);
            #pragma unroll
            for (int k2 = 0; k2 < 16; k2++) {
                float v = stg[rl * 65 + cc0 + k2];
                __nv_bfloat16 h = __float2bfloat16(v);
                const size_t off = (size_t)pix * HALF + g * 64 + cc0 + k2;
                pthi[off] = h;
                ptlo[off] = __float2bfloat16(v - __bfloat162float(h));
            }
        }
    }
}

// ==================== launch ====================
extern "C" void kernel_launch(void* const* d_in, const int* in_sizes, int n_in,
                              void* d_out, int out_size)
{
    const float* x   = (const float*)d_in[0];
    const float* q_w = (const float*)d_in[1];
    const float* q_g = (const float*)d_in[2];
    const float* q_b = (const float*)d_in[3];
    const float* q_m = (const float*)d_in[4];
    const float* q_v = (const float*)d_in[5];
    const float* k_w = (const float*)d_in[6];
    const float* k_g = (const float*)d_in[7];
    const float* k_b = (const float*)d_in[8];
    const float* k_m = (const float*)d_in[9];
    const float* k_v = (const float*)d_in[10];
    const float* v_w = (const float*)d_in[11];
    const float* v_g = (const float*)d_in[12];
    const float* v_b = (const float*)d_in[13];
    const float* v_m = (const float*)d_in[14];
    const float* v_v = (const float*)d_in[15];
    const float* o_w = (const float*)d_in[16];
    const float* o_g = (const float*)d_in[17];
    const float* o_b = (const float*)d_in[18];
    const float* o_m = (const float*)d_in[19];
    const float* o_v = (const float*)d_in[20];
    float* out = (float*)d_out;

    __nv_bfloat16 *xthi, *xtlo, *qthi, *qtlo, *pthi, *ptlo, *ahi, *alo, *kpbh, *kpbl;
    __nv_bfloat16 (*whi)[CIN * HALF], (*wlo)[CIN * HALF];
    float *gkp, *gvp;
    cudaGetSymbolAddress((void**)&xthi, g_xthi);
    cudaGetSymbolAddress((void**)&xtlo, g_xtlo);
    cudaGetSymbolAddress((void**)&qthi, g_qthi);
    cudaGetSymbolAddress((void**)&qtlo, g_qtlo);
    cudaGetSymbolAddress((void**)&pthi, g_pthi);
    cudaGetSymbolAddress((void**)&ptlo, g_ptlo);
    cudaGetSymbolAddress((void**)&ahi, g_ahi);
    cudaGetSymbolAddress((void**)&alo, g_alo);
    cudaGetSymbolAddress((void**)&kpbh, g_kpbh);
    cudaGetSymbolAddress((void**)&kpbl, g_kpbl);
    cudaGetSymbolAddress((void**)&whi, g_whi);
    cudaGetSymbolAddress((void**)&wlo, g_wlo);
    cudaGetSymbolAddress((void**)&gkp, g_kp);
    cudaGetSymbolAddress((void**)&gvp, g_vp);

    const float qscale = 0.044194173824159216f;   // 512^-0.5

    // conversions
    conv_w4_kernel<<<dim3(512, 4), 256>>>(q_w, k_w, v_w, o_w, (__nv_bfloat16*)whi, (__nv_bfloat16*)wlo);
    conv_x_kernel<<<dim3(NPIX / 32, CIN / 32), dim3(32, 8)>>>(x, xthi, xtlo);
    zero_pool_kernel<<<64, 256>>>(gkp, gvp);

    // fused q/k/v projections
    QKVParams p;
    p.whi[0] = whi[0]; p.whi[1] = whi[1]; p.whi[2] = whi[2];
    p.wlo[0] = wlo[0]; p.wlo[1] = wlo[1]; p.wlo[2] = wlo[2];
    p.gg[0] = q_g; p.gg[1] = k_g; p.gg[2] = v_g;
    p.bb[0] = q_b; p.bb[1] = k_b; p.bb[2] = v_b;
    p.mm[0] = q_m; p.mm[1] = k_m; p.mm[2] = v_m;
    p.vv[0] = q_v; p.vv[1] = k_v; p.vv[2] = v_v;

    cudaFuncSetAttribute(proj_qkv, cudaFuncAttributeMaxDynamicSharedMemorySize, PROJ_SMEM);
    proj_qkv<<<dim3(6, NPIX / 128), 256, PROJ_SMEM>>>(
        p, xthi, xtlo, qthi, qtlo, gkp, gvp, qscale);

    // kp -> bf16 [patch][c]
    kconv_kernel<<<64, 256>>>(gkp, kpbh, kpbl);

    // attn via mma.sync
    cudaFuncSetAttribute(attn_mma, cudaFuncAttributeMaxDynamicSharedMemorySize, AT_SMEM);
    attn_mma<<<dim3(8, NUM), 256, AT_SMEM>>>(qthi, qtlo, kpbh, kpbl, ahi, alo);

    // flash v4 (warp-local softmax)
    cudaFuncSetAttribute(flash4_kernel, cudaFuncAttributeMaxDynamicSharedMemorySize, F4_TOTAL);
    flash4_kernel<<<dim3(8, NUM), 256, F4_TOTAL>>>(ahi, alo, gvp, pthi, ptlo);

    // o projection + residual -> d_out
    cudaFuncSetAttribute(proj_o<HALF>, cudaFuncAttributeMaxDynamicSharedMemorySize, PROJ_SMEM);
    proj_o<HALF><<<dim3(CIN / 128, NPIX / 128), 256, PROJ_SMEM>>>(
        whi[3], wlo[3], pthi, ptlo, o_g, o_b, o_m, o_v, out, x);
}